// round 1
// baseline (speedup 1.0000x reference)
#include <cuda_runtime.h>
#include <cuda_bf16.h>
#include <math.h>

// ---------------- problem constants ----------------
#define S_LEN   2048
#define D_DIM   2048
#define H_N     16
#define NOPE_D  128
#define ROPE_D  64
#define QK_D    192           // NOPE + ROPE
#define VH_D    128
#define QLORA   1536
#define KVLORA  512
#define KVD     576           // KVLORA + ROPE
#define QUP_N   (H_N*QK_D)    // 3072
#define KVUP_N  (H_N*(NOPE_D+VH_D)) // 4096
#define ATTN_N  (H_N*VH_D)    // 2048

// ---------------- scratch (static device globals; no allocs) ----------------
__device__ float g_qdown[S_LEN*QLORA];
__device__ float g_q    [S_LEN*QUP_N];
__device__ float g_kv   [S_LEN*KVD];
__device__ float g_kvn  [S_LEN*KVLORA];
__device__ float g_kvup [S_LEN*KVUP_N];
__device__ float g_attn [S_LEN*ATTN_N];

// ---------------- NT SGEMM with fused bias: C[M,N] = A[M,K] * B[N,K]^T + bias[N] ----------------
// 64x64 tile, BK=16, 256 threads, 4x4 per thread.
#define GBM 64
#define GBN 64
#define GBK 16

__global__ void __launch_bounds__(256) mla_gemm_nt_bias(
    const float* __restrict__ A, const float* __restrict__ B,
    const float* __restrict__ bias, float* __restrict__ C,
    int M, int N, int K)
{
    __shared__ float As[GBK][GBM + 4];
    __shared__ float Bs[GBK][GBN + 4];

    const int tid = threadIdx.x;
    const int tx = tid & 15;
    const int ty = tid >> 4;
    const int brow = blockIdx.y * GBM;
    const int bcol = blockIdx.x * GBN;

    const int lr = tid >> 2;           // 0..63
    const int lc = (tid & 3) << 2;     // 0,4,8,12

    const float* Aptr = A + (size_t)(brow + lr) * K + lc;
    const float* Bptr = B + (size_t)(bcol + lr) * K + lc;

    float acc[4][4] = {};

    for (int k0 = 0; k0 < K; k0 += GBK) {
        float4 av = *(const float4*)(Aptr + k0);
        float4 bv = *(const float4*)(Bptr + k0);
        As[lc+0][lr] = av.x; As[lc+1][lr] = av.y; As[lc+2][lr] = av.z; As[lc+3][lr] = av.w;
        Bs[lc+0][lr] = bv.x; Bs[lc+1][lr] = bv.y; Bs[lc+2][lr] = bv.z; Bs[lc+3][lr] = bv.w;
        __syncthreads();
#pragma unroll
        for (int kk = 0; kk < GBK; kk++) {
            float4 a = *(const float4*)&As[kk][ty * 4];
            float4 b = *(const float4*)&Bs[kk][tx * 4];
            acc[0][0] = fmaf(a.x, b.x, acc[0][0]);
            acc[0][1] = fmaf(a.x, b.y, acc[0][1]);
            acc[0][2] = fmaf(a.x, b.z, acc[0][2]);
            acc[0][3] = fmaf(a.x, b.w, acc[0][3]);
            acc[1][0] = fmaf(a.y, b.x, acc[1][0]);
            acc[1][1] = fmaf(a.y, b.y, acc[1][1]);
            acc[1][2] = fmaf(a.y, b.z, acc[1][2]);
            acc[1][3] = fmaf(a.y, b.w, acc[1][3]);
            acc[2][0] = fmaf(a.z, b.x, acc[2][0]);
            acc[2][1] = fmaf(a.z, b.y, acc[2][1]);
            acc[2][2] = fmaf(a.z, b.z, acc[2][2]);
            acc[2][3] = fmaf(a.z, b.w, acc[2][3]);
            acc[3][0] = fmaf(a.w, b.x, acc[3][0]);
            acc[3][1] = fmaf(a.w, b.y, acc[3][1]);
            acc[3][2] = fmaf(a.w, b.z, acc[3][2]);
            acc[3][3] = fmaf(a.w, b.w, acc[3][3]);
        }
        __syncthreads();
    }

#pragma unroll
    for (int i = 0; i < 4; i++) {
        int row = brow + ty * 4 + i;
        float* crow = C + (size_t)row * N + bcol + tx * 4;
        const float* brow_b = bias + bcol + tx * 4;
#pragma unroll
        for (int j = 0; j < 4; j++)
            crow[j] = acc[i][j] + brow_b[j];
    }
}

// ---------------- RMSNorm over last dim L (row per block) ----------------
__global__ void __launch_bounds__(256) mla_rmsnorm(
    const float* __restrict__ X, int ldx,
    const float* __restrict__ w,
    float* __restrict__ Y, int ldy, int L)
{
    const int row = blockIdx.x;
    const float* x = X + (size_t)row * ldx;
    float ss = 0.f;
    for (int c = threadIdx.x; c < L; c += blockDim.x) {
        float v = x[c];
        ss = fmaf(v, v, ss);
    }
#pragma unroll
    for (int o = 16; o; o >>= 1) ss += __shfl_xor_sync(0xffffffffu, ss, o);

    __shared__ float red[8];
    __shared__ float s_inv;
    if ((threadIdx.x & 31) == 0) red[threadIdx.x >> 5] = ss;
    __syncthreads();
    if (threadIdx.x == 0) {
        float t = 0.f;
#pragma unroll
        for (int i = 0; i < 8; i++) t += red[i];
        s_inv = rsqrtf(t / (float)L + 1e-6f);
    }
    __syncthreads();
    float inv = s_inv;
    float* y = Y + (size_t)row * ldy;
    for (int c = threadIdx.x; c < L; c += blockDim.x)
        y[c] = w[c] * (x[c] * inv);
}

// ---------------- RoPE (in place) ----------------
// q layout [S, H*192]; rope applies to cols h*192+128 .. h*192+191 (32 pairs)
__global__ void mla_rope_q(float* __restrict__ q,
                           const float* __restrict__ fc,
                           const float* __restrict__ fs)
{
    int idx = blockIdx.x * blockDim.x + threadIdx.x;   // S*H*32 total
    int i = idx & 31;
    int h = (idx >> 5) & (H_N - 1);
    int s = idx >> 9;
    float c = fc[s * 32 + i];
    float sn = fs[s * 32 + i];
    float* p = q + (size_t)s * QUP_N + h * QK_D + NOPE_D + 2 * i;
    float x0 = p[0], x1 = p[1];
    p[0] = x0 * c - x1 * sn;
    p[1] = x0 * sn + x1 * c;
}

// kv layout [S, 576]; rope applies to cols 512..575 (32 pairs, shared across heads)
__global__ void mla_rope_k(float* __restrict__ kv,
                           const float* __restrict__ fc,
                           const float* __restrict__ fs)
{
    int idx = blockIdx.x * blockDim.x + threadIdx.x;   // S*32 total
    int i = idx & 31;
    int s = idx >> 5;
    float c = fc[s * 32 + i];
    float sn = fs[s * 32 + i];
    float* p = kv + (size_t)s * KVD + KVLORA + 2 * i;
    float x0 = p[0], x1 = p[1];
    p[0] = x0 * c - x1 * sn;
    p[1] = x0 * sn + x1 * c;
}

// ---------------- Flash attention (causal), f32 ----------------
// grid: (S/64, H). block: 256 (16x16). Per CTA: 64 q rows vs streamed 64-row kv blocks.
// Q read from g_q (row stride 3072, offset h*192).
// K assembled from g_kvup (k_nope, 128) + g_kv (k_pe, 64). V from g_kvup (+128).
#define FBM 64
#define FBN 64
#define QSTR 196
#define KSTR 196
#define PSTR 68
#define FLASH_SMEM ((FBM*QSTR + FBN*KSTR + FBN*128 + FBM*PSTR) * 4)

extern __shared__ float fsm[];

__global__ void __launch_bounds__(256, 1) mla_flash(
    const float* __restrict__ Q,
    const float* __restrict__ KVUP,
    const float* __restrict__ KV,
    float* __restrict__ Oout)
{
    float* Qs = fsm;
    float* Ks = Qs + FBM * QSTR;
    float* Vs = Ks + FBN * KSTR;
    float* Ps = Vs + FBN * 128;

    const int h = blockIdx.y;
    const int qb = blockIdx.x;
    const int qbase = qb * FBM;
    const int tid = threadIdx.x;
    const int tx = tid & 15;
    const int ty = tid >> 4;

    // load Q block: 64 rows x 192 floats
    for (int idx = tid; idx < FBM * 48; idx += 256) {
        int r = idx / 48, c4 = idx % 48;
        float4 v = *(const float4*)(Q + (size_t)(qbase + r) * QUP_N + h * QK_D + c4 * 4);
        *(float4*)&Qs[r * QSTR + c4 * 4] = v;
    }

    float o[4][8] = {};
    float m[4] = { -3.0e38f, -3.0e38f, -3.0e38f, -3.0e38f };
    float l[4] = { 0.f, 0.f, 0.f, 0.f };
    const float scale = 0.07216878364870322f;  // 192^-0.5

    for (int kb = 0; kb <= qb; kb++) {
        const int kbase = kb * FBN;

        // load K block: k_nope (128) then k_pe (64)
        for (int idx = tid; idx < FBN * 48; idx += 256) {
            int r = idx / 48, c4 = idx % 48;
            float4 v;
            if (c4 < 32)
                v = *(const float4*)(KVUP + (size_t)(kbase + r) * KVUP_N + h * 256 + c4 * 4);
            else
                v = *(const float4*)(KV + (size_t)(kbase + r) * KVD + KVLORA + (c4 - 32) * 4);
            *(float4*)&Ks[r * KSTR + c4 * 4] = v;
        }
        // load V block: 64 rows x 128
        for (int idx = tid; idx < FBN * 32; idx += 256) {
            int r = idx / 32, c4 = idx % 32;
            float4 v = *(const float4*)(KVUP + (size_t)(kbase + r) * KVUP_N + h * 256 + 128 + c4 * 4);
            *(float4*)&Vs[r * 128 + c4 * 4] = v;
        }
        __syncthreads();

        // S = Q K^T : rows ty+16i, cols tx+16j
        float sc[4][4] = {};
#pragma unroll 8
        for (int d = 0; d < QK_D; d += 4) {
            float4 a[4], b[4];
#pragma unroll
            for (int i = 0; i < 4; i++) a[i] = *(const float4*)&Qs[(ty + 16 * i) * QSTR + d];
#pragma unroll
            for (int j = 0; j < 4; j++) b[j] = *(const float4*)&Ks[(tx + 16 * j) * KSTR + d];
#pragma unroll
            for (int i = 0; i < 4; i++)
#pragma unroll
                for (int j = 0; j < 4; j++)
                    sc[i][j] = fmaf(a[i].x, b[j].x,
                               fmaf(a[i].y, b[j].y,
                               fmaf(a[i].z, b[j].z,
                               fmaf(a[i].w, b[j].w, sc[i][j]))));
        }

        const bool diag = (kb == qb);
#pragma unroll
        for (int i = 0; i < 4; i++) {
            const int rloc = ty + 16 * i;
            float pv[4];
            float rm = -3.0e38f;
#pragma unroll
            for (int j = 0; j < 4; j++) {
                float v = sc[i][j] * scale;
                if (diag && (tx + 16 * j) > rloc) v = -3.0e38f;
                pv[j] = v;
                rm = fmaxf(rm, v);
            }
#pragma unroll
            for (int off = 8; off; off >>= 1)
                rm = fmaxf(rm, __shfl_xor_sync(0xffffffffu, rm, off));
            float mn = fmaxf(m[i], rm);
            float alpha = __expf(m[i] - mn);
            float rs = 0.f;
#pragma unroll
            for (int j = 0; j < 4; j++) {
                float p = __expf(pv[j] - mn);
                Ps[rloc * PSTR + tx + 16 * j] = p;
                rs += p;
            }
#pragma unroll
            for (int off = 8; off; off >>= 1)
                rs += __shfl_xor_sync(0xffffffffu, rs, off);
            l[i] = l[i] * alpha + rs;
            m[i] = mn;
#pragma unroll
            for (int j = 0; j < 8; j++) o[i][j] *= alpha;
        }
        __syncthreads();

        // O += P V : O rows ty+16i, cols tx*8 .. tx*8+7
#pragma unroll 4
        for (int k = 0; k < FBN; k++) {
            float4 v0 = *(const float4*)&Vs[k * 128 + tx * 8];
            float4 v1 = *(const float4*)&Vs[k * 128 + tx * 8 + 4];
#pragma unroll
            for (int i = 0; i < 4; i++) {
                float p = Ps[(ty + 16 * i) * PSTR + k];
                o[i][0] = fmaf(p, v0.x, o[i][0]);
                o[i][1] = fmaf(p, v0.y, o[i][1]);
                o[i][2] = fmaf(p, v0.z, o[i][2]);
                o[i][3] = fmaf(p, v0.w, o[i][3]);
                o[i][4] = fmaf(p, v1.x, o[i][4]);
                o[i][5] = fmaf(p, v1.y, o[i][5]);
                o[i][6] = fmaf(p, v1.z, o[i][6]);
                o[i][7] = fmaf(p, v1.w, o[i][7]);
            }
        }
        __syncthreads();
    }

    // write out: attn[s][h*128 + c]
#pragma unroll
    for (int i = 0; i < 4; i++) {
        float inv = 1.0f / l[i];
        int row = qbase + ty + 16 * i;
        float* dst = Oout + (size_t)row * ATTN_N + h * VH_D + tx * 8;
        float4 r0 = make_float4(o[i][0] * inv, o[i][1] * inv, o[i][2] * inv, o[i][3] * inv);
        float4 r1 = make_float4(o[i][4] * inv, o[i][5] * inv, o[i][6] * inv, o[i][7] * inv);
        *(float4*)dst = r0;
        *(float4*)(dst + 4) = r1;
    }
}

// ---------------- launch ----------------
extern "C" void kernel_launch(void* const* d_in, const int* in_sizes, int n_in,
                              void* d_out, int out_size)
{
    const float* x          = (const float*)d_in[0];
    const float* fcos       = (const float*)d_in[2];
    const float* fsin       = (const float*)d_in[3];
    const float* wq_down_w  = (const float*)d_in[5];
    const float* wq_down_b  = (const float*)d_in[6];
    const float* q_norm_w   = (const float*)d_in[7];
    const float* wq_up_w    = (const float*)d_in[8];
    const float* wq_up_b    = (const float*)d_in[9];
    const float* wkv_down_w = (const float*)d_in[10];
    const float* wkv_down_b = (const float*)d_in[11];
    const float* kv_norm_w  = (const float*)d_in[12];
    const float* wkv_up_w   = (const float*)d_in[13];
    const float* wkv_up_b   = (const float*)d_in[14];
    const float* wo_w       = (const float*)d_in[15];
    const float* wo_b       = (const float*)d_in[16];
    float* out = (float*)d_out;

    float *qdown, *q, *kv, *kvn, *kvup, *attn;
    cudaGetSymbolAddress((void**)&qdown, g_qdown);
    cudaGetSymbolAddress((void**)&q,     g_q);
    cudaGetSymbolAddress((void**)&kv,    g_kv);
    cudaGetSymbolAddress((void**)&kvn,   g_kvn);
    cudaGetSymbolAddress((void**)&kvup,  g_kvup);
    cudaGetSymbolAddress((void**)&attn,  g_attn);

    cudaFuncSetAttribute(mla_flash, cudaFuncAttributeMaxDynamicSharedMemorySize, FLASH_SMEM);

    // 1. q_down = x @ wq_down^T + b      [2048,1536]
    mla_gemm_nt_bias<<<dim3(QLORA / GBN, S_LEN / GBM), 256>>>(
        x, wq_down_w, wq_down_b, qdown, S_LEN, QLORA, D_DIM);
    // 2. kv = x @ wkv_down^T + b         [2048,576]
    mla_gemm_nt_bias<<<dim3(KVD / GBN, S_LEN / GBM), 256>>>(
        x, wkv_down_w, wkv_down_b, kv, S_LEN, KVD, D_DIM);
    // 3. rmsnorm q_down (in place)
    mla_rmsnorm<<<S_LEN, 256>>>(qdown, QLORA, q_norm_w, qdown, QLORA, QLORA);
    // 4. rmsnorm kv_lat -> kvn
    mla_rmsnorm<<<S_LEN, 256>>>(kv, KVD, kv_norm_w, kvn, KVLORA, KVLORA);
    // 5. q = qdown @ wq_up^T + b         [2048,3072]
    mla_gemm_nt_bias<<<dim3(QUP_N / GBN, S_LEN / GBM), 256>>>(
        qdown, wq_up_w, wq_up_b, q, S_LEN, QUP_N, QLORA);
    // 6. kv_up = kvn @ wkv_up^T + b      [2048,4096]
    mla_gemm_nt_bias<<<dim3(KVUP_N / GBN, S_LEN / GBM), 256>>>(
        kvn, wkv_up_w, wkv_up_b, kvup, S_LEN, KVUP_N, KVLORA);
    // 7. rope on q_pe (in place), 8. rope on k_pe (in place)
    mla_rope_q<<<(S_LEN * H_N * 32) / 256, 256>>>(q, fcos, fsin);
    mla_rope_k<<<(S_LEN * 32) / 256, 256>>>(kv, fcos, fsin);
    // 9. causal flash attention -> attn  [2048,2048]
    mla_flash<<<dim3(S_LEN / FBM, H_N), 256, FLASH_SMEM>>>(q, kvup, kv, attn);
    // 10. out = attn @ wo^T + b          [2048,2048]
    mla_gemm_nt_bias<<<dim3(D_DIM / GBN, S_LEN / GBM), 256>>>(
        attn, wo_w, wo_b, out, S_LEN, D_DIM, ATTN_N);
}

// round 3
// speedup vs baseline: 1.6061x; 1.6061x over previous
#include <cuda_runtime.h>
#include <cuda_bf16.h>
#include <cstdint>
#include <math.h>

// ---------------- problem constants ----------------
#define S_LEN   2048
#define D_DIM   2048
#define H_N     16
#define NOPE_D  128
#define ROPE_D  64
#define QK_D    192
#define VH_D    128
#define QLORA   1536
#define KVLORA  512
#define KVD     576
#define QUP_N   (H_N*QK_D)            // 3072
#define KVUP_N  (H_N*(NOPE_D+VH_D))   // 4096
#define ATTN_N  (H_N*VH_D)            // 2048

typedef __nv_bfloat16 bf16;

// ---------------- scratch ----------------
__device__ float g_qdown[S_LEN*QLORA];
__device__ float g_q    [S_LEN*QUP_N];
__device__ float g_kv   [S_LEN*KVD];
__device__ float g_kvup [S_LEN*KVUP_N];

__device__ bf16 g_xh[S_LEN*D_DIM],      g_xl[S_LEN*D_DIM];
__device__ bf16 g_qdnh[S_LEN*QLORA],    g_qdnl[S_LEN*QLORA];
__device__ bf16 g_kvnh[S_LEN*KVLORA],   g_kvnl[S_LEN*KVLORA];
__device__ bf16 g_attnh[S_LEN*ATTN_N],  g_attnl[S_LEN*ATTN_N];

__device__ bf16 g_wqdh[QLORA*D_DIM],    g_wqdl[QLORA*D_DIM];
__device__ bf16 g_wkvdh[KVD*D_DIM],     g_wkvdl[KVD*D_DIM];
__device__ bf16 g_wquh[QUP_N*QLORA],    g_wqul[QUP_N*QLORA];
__device__ bf16 g_wkvuh[KVUP_N*KVLORA], g_wkvul[KVUP_N*KVLORA];
__device__ bf16 g_woh[D_DIM*ATTN_N],    g_wol[D_DIM*ATTN_N];

// ---------------- PTX helpers (arch-agnostic: sm_80+ PTX only) ----------------
__device__ __forceinline__ uint32_t smem_u32(const void* p) {
    uint32_t a;
    asm("{ .reg .u64 t; cvta.to.shared.u64 t, %1; cvt.u32.u64 %0, t; }" : "=r"(a) : "l"(p));
    return a;
}

#define CP_ASYNC16(dst, src, sz) \
    asm volatile("cp.async.cg.shared.global [%0], [%1], 16, %2;" \
        :: "r"(dst), "l"(src), "r"(sz) : "memory")
#define CP_COMMIT()  asm volatile("cp.async.commit_group;" ::: "memory")
#define CP_WAIT(n)   asm volatile("cp.async.wait_group %0;" :: "n"(n) : "memory")

__device__ __forceinline__ void ldsm4(uint32_t addr, uint32_t* f) {
    asm volatile("ldmatrix.sync.aligned.m8n8.x4.shared.b16 {%0,%1,%2,%3}, [%4];"
        : "=r"(f[0]), "=r"(f[1]), "=r"(f[2]), "=r"(f[3]) : "r"(addr));
}

#define MMA16816(d, a, b0, b1) \
    asm volatile("mma.sync.aligned.m16n8k16.row.col.f32.bf16.bf16.f32 " \
        "{%0,%1,%2,%3}, {%4,%5,%6,%7}, {%8,%9}, {%0,%1,%2,%3};" \
        : "+f"((d)[0]), "+f"((d)[1]), "+f"((d)[2]), "+f"((d)[3]) \
        : "r"((a)[0]), "r"((a)[1]), "r"((a)[2]), "r"((a)[3]), "r"(b0), "r"(b1))

// smem chunk swizzle: tile = 128 rows x 4 chunks of 16B. Bijective per 8-row
// ldmatrix phase AND per 8-lane store phase (rows r,r+1 x 4 chunks).
__device__ __forceinline__ uint32_t off16(int r, int c) {
    return (uint32_t)(r * 4 + ((((r >> 1) & 3) ^ c)));
}

// ---------------- split f32 -> bf16 hi/lo ----------------
__global__ void split_f32(const float* __restrict__ x, bf16* __restrict__ h,
                          bf16* __restrict__ l, int n4)
{
    int i = blockIdx.x * blockDim.x + threadIdx.x;
    if (i >= n4) return;
    float4 v = ((const float4*)x)[i];
    bf16 h0 = __float2bfloat16(v.x), h1 = __float2bfloat16(v.y);
    bf16 h2 = __float2bfloat16(v.z), h3 = __float2bfloat16(v.w);
    bf16 l0 = __float2bfloat16(v.x - __bfloat162float(h0));
    bf16 l1 = __float2bfloat16(v.y - __bfloat162float(h1));
    bf16 l2 = __float2bfloat16(v.z - __bfloat162float(h2));
    bf16 l3 = __float2bfloat16(v.w - __bfloat162float(h3));
    bf16 hh[4] = {h0, h1, h2, h3};
    bf16 ll[4] = {l0, l1, l2, l3};
    ((uint2*)h)[i] = *(uint2*)hh;
    ((uint2*)l)[i] = *(uint2*)ll;
}

// ---------------- HMMA split-bf16 NT GEMM ----------------
// C[M,N] = A[M,K] B[N,K]^T + bias.  3 passes: Ah*Bh + Ah*Bl + Al*Bh.
// 128x128 tile, BK=32, 256 thr (8 warps 2x4), warp tile 64x32, cp.async double buffer.
#define GM_SMEM (2*4*8192)   // 2 stages x 4 tiles (Ah,Al,Bh,Bl) x 8KB

__global__ void __launch_bounds__(256) gemm_mma(
    const bf16* __restrict__ Ah, const bf16* __restrict__ Al,
    const bf16* __restrict__ Bh, const bf16* __restrict__ Bl,
    const float* __restrict__ bias, float* __restrict__ C,
    int N, int K)
{
    extern __shared__ __align__(1024) char sm[];
    const uint32_t smb = smem_u32(sm);

    const int tid = threadIdx.x;
    const int lane = tid & 31;
    const int wid = tid >> 5;
    const int warp_m = wid & 1;       // 0..1  -> 64 rows
    const int warp_n = wid >> 1;      // 0..3  -> 32 cols
    const int brow = blockIdx.y * 128;
    const int bcol = blockIdx.x * 128;

    // per-thread global-load coords (2 chunks per tile per thread)
    const int r0g = tid >> 2;            // rows: it0 -> tid/4, it1 -> tid/4 + 64
    const int c0g = tid & 3;

    // fragment smem offsets (bytes, relative to tile base)
    uint32_t aoff[4][2], boff[2][2];
#pragma unroll
    for (int mt = 0; mt < 4; mt++)
#pragma unroll
        for (int ks = 0; ks < 2; ks++) {
            int rr = warp_m * 64 + mt * 16 + (lane & 15);
            int cc = ks * 2 + (lane >> 4);
            aoff[mt][ks] = off16(rr, cc) * 16;
        }
#pragma unroll
    for (int g = 0; g < 2; g++)
#pragma unroll
        for (int ks = 0; ks < 2; ks++) {
            int rr = warp_n * 32 + g * 16 + (lane & 15);
            int cc = ks * 2 + (lane >> 4);
            boff[g][ks] = off16(rr, cc) * 16;
        }

    float acc[4][4][4];
#pragma unroll
    for (int i = 0; i < 4; i++)
#pragma unroll
        for (int j = 0; j < 4; j++)
#pragma unroll
            for (int k = 0; k < 4; k++) acc[i][j][k] = 0.f;

    const int KT = K >> 5;

    auto load_stage = [&](int s, int k0) {
        uint32_t base = smb + s * 32768;
#pragma unroll
        for (int it = 0; it < 2; it++) {
            int r = r0g + it * 64;
            int c = c0g;
            uint32_t doff = off16(r, c) * 16;
            size_t ga = (size_t)(brow + r) * K + k0 + c * 8;
            CP_ASYNC16(base + doff,         Ah + ga, 16);
            CP_ASYNC16(base + 8192 + doff,  Al + ga, 16);
            int gr = bcol + r;
            int ok = (gr < N) ? 16 : 0;
            size_t gb = (size_t)(ok ? gr : 0) * K + k0 + c * 8;
            CP_ASYNC16(base + 16384 + doff, Bh + gb, ok);
            CP_ASYNC16(base + 24576 + doff, Bl + gb, ok);
        }
        CP_COMMIT();
    };

    load_stage(0, 0);

    int buf = 0;
    for (int kt = 0; kt < KT; kt++) {
        if (kt + 1 < KT) {
            load_stage(buf ^ 1, (kt + 1) * 32);
            CP_WAIT(1);
        } else {
            CP_WAIT(0);
        }
        __syncthreads();

        uint32_t st = smb + buf * 32768;
#pragma unroll
        for (int pass = 0; pass < 3; pass++) {
            uint32_t aBase = st + (pass == 2 ? 8192 : 0);
            uint32_t bBase = st + (pass == 1 ? 24576 : 16384);
            uint32_t af[4][2][4], bfr[2][2][4];
#pragma unroll
            for (int mt = 0; mt < 4; mt++)
#pragma unroll
                for (int ks = 0; ks < 2; ks++)
                    ldsm4(aBase + aoff[mt][ks], af[mt][ks]);
#pragma unroll
            for (int g = 0; g < 2; g++)
#pragma unroll
                for (int ks = 0; ks < 2; ks++)
                    ldsm4(bBase + boff[g][ks], bfr[g][ks]);
#pragma unroll
            for (int mt = 0; mt < 4; mt++)
#pragma unroll
                for (int nt = 0; nt < 4; nt++) {
                    int g = nt >> 1, hf = nt & 1;
#pragma unroll
                    for (int ks = 0; ks < 2; ks++)
                        MMA16816(acc[mt][nt], af[mt][ks],
                                 bfr[g][ks][hf], bfr[g][ks][hf + 2]);
                }
        }
        __syncthreads();
        buf ^= 1;
    }

    // epilogue: write f32 + bias
#pragma unroll
    for (int mt = 0; mt < 4; mt++) {
#pragma unroll
        for (int nt = 0; nt < 4; nt++) {
            int row = brow + warp_m * 64 + mt * 16 + (lane >> 2);
            int col = bcol + warp_n * 32 + nt * 8 + (lane & 3) * 2;
            if (col < N) {
                float b0 = bias[col], b1 = bias[col + 1];
                float2 v0 = make_float2(acc[mt][nt][0] + b0, acc[mt][nt][1] + b1);
                float2 v1 = make_float2(acc[mt][nt][2] + b0, acc[mt][nt][3] + b1);
                *(float2*)(C + (size_t)row * N + col) = v0;
                *(float2*)(C + (size_t)(row + 8) * N + col) = v1;
            }
        }
    }
}

// ---------------- RMSNorm -> split bf16 hi/lo ----------------
__global__ void __launch_bounds__(256) mla_rmsnorm_split(
    const float* __restrict__ X, int ldx, const float* __restrict__ w,
    bf16* __restrict__ Yh, bf16* __restrict__ Yl, int L)
{
    const int row = blockIdx.x;
    const float* x = X + (size_t)row * ldx;
    float ss = 0.f;
    for (int c = threadIdx.x; c < L; c += blockDim.x) {
        float v = x[c];
        ss = fmaf(v, v, ss);
    }
#pragma unroll
    for (int o = 16; o; o >>= 1) ss += __shfl_xor_sync(0xffffffffu, ss, o);
    __shared__ float red[8];
    __shared__ float s_inv;
    if ((threadIdx.x & 31) == 0) red[threadIdx.x >> 5] = ss;
    __syncthreads();
    if (threadIdx.x == 0) {
        float t = 0.f;
#pragma unroll
        for (int i = 0; i < 8; i++) t += red[i];
        s_inv = rsqrtf(t / (float)L + 1e-6f);
    }
    __syncthreads();
    float inv = s_inv;
    for (int c = threadIdx.x; c < L; c += blockDim.x) {
        float val = w[c] * (x[c] * inv);
        bf16 hi = __float2bfloat16(val);
        bf16 lo = __float2bfloat16(val - __bfloat162float(hi));
        Yh[(size_t)row * L + c] = hi;
        Yl[(size_t)row * L + c] = lo;
    }
}

// ---------------- RoPE ----------------
__global__ void mla_rope_q(float* __restrict__ q, const float* __restrict__ fc,
                           const float* __restrict__ fs)
{
    int idx = blockIdx.x * blockDim.x + threadIdx.x;
    int i = idx & 31;
    int h = (idx >> 5) & (H_N - 1);
    int s = idx >> 9;
    float c = fc[s * 32 + i], sn = fs[s * 32 + i];
    float* p = q + (size_t)s * QUP_N + h * QK_D + NOPE_D + 2 * i;
    float x0 = p[0], x1 = p[1];
    p[0] = x0 * c - x1 * sn;
    p[1] = x0 * sn + x1 * c;
}
__global__ void mla_rope_k(float* __restrict__ kv, const float* __restrict__ fc,
                           const float* __restrict__ fs)
{
    int idx = blockIdx.x * blockDim.x + threadIdx.x;
    int i = idx & 31;
    int s = idx >> 5;
    float c = fc[s * 32 + i], sn = fs[s * 32 + i];
    float* p = kv + (size_t)s * KVD + KVLORA + 2 * i;
    float x0 = p[0], x1 = p[1];
    p[0] = x0 * c - x1 * sn;
    p[1] = x0 * sn + x1 * c;
}

// ---------------- Flash attention (causal), f32; epilogue writes split bf16 ----------------
#define FBM 64
#define FBN 64
#define QSTR 196
#define KSTR 196
#define PSTR 68
#define FLASH_SMEM ((FBM*QSTR + FBN*KSTR + FBN*128 + FBM*PSTR) * 4)

extern __shared__ float fsm[];

__global__ void __launch_bounds__(256, 1) mla_flash(
    const float* __restrict__ Q, const float* __restrict__ KVUP,
    const float* __restrict__ KV,
    bf16* __restrict__ Oh, bf16* __restrict__ Ol)
{
    float* Qs = fsm;
    float* Ks = Qs + FBM * QSTR;
    float* Vs = Ks + FBN * KSTR;
    float* Ps = Vs + FBN * 128;

    const int h = blockIdx.y;
    const int qb = blockIdx.x;
    const int qbase = qb * FBM;
    const int tid = threadIdx.x;
    const int tx = tid & 15;
    const int ty = tid >> 4;

    for (int idx = tid; idx < FBM * 48; idx += 256) {
        int r = idx / 48, c4 = idx % 48;
        float4 v = *(const float4*)(Q + (size_t)(qbase + r) * QUP_N + h * QK_D + c4 * 4);
        *(float4*)&Qs[r * QSTR + c4 * 4] = v;
    }

    float o[4][8] = {};
    float m[4] = { -3.0e38f, -3.0e38f, -3.0e38f, -3.0e38f };
    float l[4] = { 0.f, 0.f, 0.f, 0.f };
    const float scale = 0.07216878364870322f;

    for (int kb = 0; kb <= qb; kb++) {
        const int kbase = kb * FBN;
        for (int idx = tid; idx < FBN * 48; idx += 256) {
            int r = idx / 48, c4 = idx % 48;
            float4 v;
            if (c4 < 32)
                v = *(const float4*)(KVUP + (size_t)(kbase + r) * KVUP_N + h * 256 + c4 * 4);
            else
                v = *(const float4*)(KV + (size_t)(kbase + r) * KVD + KVLORA + (c4 - 32) * 4);
            *(float4*)&Ks[r * KSTR + c4 * 4] = v;
        }
        for (int idx = tid; idx < FBN * 32; idx += 256) {
            int r = idx / 32, c4 = idx % 32;
            float4 v = *(const float4*)(KVUP + (size_t)(kbase + r) * KVUP_N + h * 256 + 128 + c4 * 4);
            *(float4*)&Vs[r * 128 + c4 * 4] = v;
        }
        __syncthreads();

        float sc[4][4] = {};
#pragma unroll 8
        for (int d = 0; d < QK_D; d += 4) {
            float4 a[4], b[4];
#pragma unroll
            for (int i = 0; i < 4; i++) a[i] = *(const float4*)&Qs[(ty + 16 * i) * QSTR + d];
#pragma unroll
            for (int j = 0; j < 4; j++) b[j] = *(const float4*)&Ks[(tx + 16 * j) * KSTR + d];
#pragma unroll
            for (int i = 0; i < 4; i++)
#pragma unroll
                for (int j = 0; j < 4; j++)
                    sc[i][j] = fmaf(a[i].x, b[j].x, fmaf(a[i].y, b[j].y,
                               fmaf(a[i].z, b[j].z, fmaf(a[i].w, b[j].w, sc[i][j]))));
        }

        const bool diag = (kb == qb);
#pragma unroll
        for (int i = 0; i < 4; i++) {
            const int rloc = ty + 16 * i;
            float pv[4];
            float rm = -3.0e38f;
#pragma unroll
            for (int j = 0; j < 4; j++) {
                float v = sc[i][j] * scale;
                if (diag && (tx + 16 * j) > rloc) v = -3.0e38f;
                pv[j] = v;
                rm = fmaxf(rm, v);
            }
#pragma unroll
            for (int off = 8; off; off >>= 1)
                rm = fmaxf(rm, __shfl_xor_sync(0xffffffffu, rm, off));
            float mn = fmaxf(m[i], rm);
            float alpha = __expf(m[i] - mn);
            float rs = 0.f;
#pragma unroll
            for (int j = 0; j < 4; j++) {
                float p = __expf(pv[j] - mn);
                Ps[rloc * PSTR + tx + 16 * j] = p;
                rs += p;
            }
#pragma unroll
            for (int off = 8; off; off >>= 1)
                rs += __shfl_xor_sync(0xffffffffu, rs, off);
            l[i] = l[i] * alpha + rs;
            m[i] = mn;
#pragma unroll
            for (int j = 0; j < 8; j++) o[i][j] *= alpha;
        }
        __syncthreads();

#pragma unroll 4
        for (int k = 0; k < FBN; k++) {
            float4 v0 = *(const float4*)&Vs[k * 128 + tx * 8];
            float4 v1 = *(const float4*)&Vs[k * 128 + tx * 8 + 4];
#pragma unroll
            for (int i = 0; i < 4; i++) {
                float p = Ps[(ty + 16 * i) * PSTR + k];
                o[i][0] = fmaf(p, v0.x, o[i][0]);
                o[i][1] = fmaf(p, v0.y, o[i][1]);
                o[i][2] = fmaf(p, v0.z, o[i][2]);
                o[i][3] = fmaf(p, v0.w, o[i][3]);
                o[i][4] = fmaf(p, v1.x, o[i][4]);
                o[i][5] = fmaf(p, v1.y, o[i][5]);
                o[i][6] = fmaf(p, v1.z, o[i][6]);
                o[i][7] = fmaf(p, v1.w, o[i][7]);
            }
        }
        __syncthreads();
    }

#pragma unroll
    for (int i = 0; i < 4; i++) {
        float inv = 1.0f / l[i];
        int row = qbase + ty + 16 * i;
        bf16 hb[8], lb[8];
#pragma unroll
        for (int j = 0; j < 8; j++) {
            float v = o[i][j] * inv;
            hb[j] = __float2bfloat16(v);
            lb[j] = __float2bfloat16(v - __bfloat162float(hb[j]));
        }
        size_t off = (size_t)row * ATTN_N + h * VH_D + tx * 8;
        *(uint4*)(Oh + off) = *(uint4*)hb;
        *(uint4*)(Ol + off) = *(uint4*)lb;
    }
}

// ---------------- launch ----------------
static inline void split_launch(const float* src, bf16* h, bf16* l, int n) {
    int n4 = n / 4;
    split_f32<<<(n4 + 255) / 256, 256>>>(src, h, l, n4);
}

extern "C" void kernel_launch(void* const* d_in, const int* in_sizes, int n_in,
                              void* d_out, int out_size)
{
    const float* x          = (const float*)d_in[0];
    const float* fcos       = (const float*)d_in[2];
    const float* fsin       = (const float*)d_in[3];
    const float* wq_down_w  = (const float*)d_in[5];
    const float* wq_down_b  = (const float*)d_in[6];
    const float* q_norm_w   = (const float*)d_in[7];
    const float* wq_up_w    = (const float*)d_in[8];
    const float* wq_up_b    = (const float*)d_in[9];
    const float* wkv_down_w = (const float*)d_in[10];
    const float* wkv_down_b = (const float*)d_in[11];
    const float* kv_norm_w  = (const float*)d_in[12];
    const float* wkv_up_w   = (const float*)d_in[13];
    const float* wkv_up_b   = (const float*)d_in[14];
    const float* wo_w       = (const float*)d_in[15];
    const float* wo_b       = (const float*)d_in[16];
    float* out = (float*)d_out;

    float *qdown, *q, *kv, *kvup;
    bf16 *xh, *xl, *qdnh, *qdnl, *kvnh, *kvnl, *attnh, *attnl;
    bf16 *wqdh, *wqdl, *wkvdh, *wkvdl, *wquh, *wqul, *wkvuh, *wkvul, *woh, *wol;
    cudaGetSymbolAddress((void**)&qdown, g_qdown);
    cudaGetSymbolAddress((void**)&q,     g_q);
    cudaGetSymbolAddress((void**)&kv,    g_kv);
    cudaGetSymbolAddress((void**)&kvup,  g_kvup);
    cudaGetSymbolAddress((void**)&xh, g_xh);       cudaGetSymbolAddress((void**)&xl, g_xl);
    cudaGetSymbolAddress((void**)&qdnh, g_qdnh);   cudaGetSymbolAddress((void**)&qdnl, g_qdnl);
    cudaGetSymbolAddress((void**)&kvnh, g_kvnh);   cudaGetSymbolAddress((void**)&kvnl, g_kvnl);
    cudaGetSymbolAddress((void**)&attnh, g_attnh); cudaGetSymbolAddress((void**)&attnl, g_attnl);
    cudaGetSymbolAddress((void**)&wqdh, g_wqdh);   cudaGetSymbolAddress((void**)&wqdl, g_wqdl);
    cudaGetSymbolAddress((void**)&wkvdh, g_wkvdh); cudaGetSymbolAddress((void**)&wkvdl, g_wkvdl);
    cudaGetSymbolAddress((void**)&wquh, g_wquh);   cudaGetSymbolAddress((void**)&wqul, g_wqul);
    cudaGetSymbolAddress((void**)&wkvuh, g_wkvuh); cudaGetSymbolAddress((void**)&wkvul, g_wkvul);
    cudaGetSymbolAddress((void**)&woh, g_woh);     cudaGetSymbolAddress((void**)&wol, g_wol);

    cudaFuncSetAttribute(mla_flash, cudaFuncAttributeMaxDynamicSharedMemorySize, FLASH_SMEM);
    cudaFuncSetAttribute(gemm_mma, cudaFuncAttributeMaxDynamicSharedMemorySize, GM_SMEM);

    // split inputs + weights to bf16 hi/lo
    split_launch(x,          xh,    xl,    S_LEN * D_DIM);
    split_launch(wq_down_w,  wqdh,  wqdl,  QLORA * D_DIM);
    split_launch(wkv_down_w, wkvdh, wkvdl, KVD * D_DIM);
    split_launch(wq_up_w,    wquh,  wqul,  QUP_N * QLORA);
    split_launch(wkv_up_w,   wkvuh, wkvul, KVUP_N * KVLORA);
    split_launch(wo_w,       woh,   wol,   D_DIM * ATTN_N);

    // 1. q_down = x @ wq_down^T + b     [2048,1536]
    gemm_mma<<<dim3(QLORA / 128, S_LEN / 128), 256, GM_SMEM>>>(
        xh, xl, wqdh, wqdl, wq_down_b, qdown, QLORA, D_DIM);
    // 2. kv = x @ wkv_down^T + b        [2048,576]  (ragged N)
    gemm_mma<<<dim3((KVD + 127) / 128, S_LEN / 128), 256, GM_SMEM>>>(
        xh, xl, wkvdh, wkvdl, wkv_down_b, kv, KVD, D_DIM);
    // 3. rmsnorm q_down -> split bf16
    mla_rmsnorm_split<<<S_LEN, 256>>>(qdown, QLORA, q_norm_w, qdnh, qdnl, QLORA);
    // 4. rmsnorm kv_lat -> split bf16
    mla_rmsnorm_split<<<S_LEN, 256>>>(kv, KVD, kv_norm_w, kvnh, kvnl, KVLORA);
    // 5. q = qdown_n @ wq_up^T + b      [2048,3072]
    gemm_mma<<<dim3(QUP_N / 128, S_LEN / 128), 256, GM_SMEM>>>(
        qdnh, qdnl, wquh, wqul, wq_up_b, q, QUP_N, QLORA);
    // 6. kv_up = kvn @ wkv_up^T + b     [2048,4096]
    gemm_mma<<<dim3(KVUP_N / 128, S_LEN / 128), 256, GM_SMEM>>>(
        kvnh, kvnl, wkvuh, wkvul, wkv_up_b, kvup, KVUP_N, KVLORA);
    // 7/8. rope
    mla_rope_q<<<(S_LEN * H_N * 32) / 256, 256>>>(q, fcos, fsin);
    mla_rope_k<<<(S_LEN * 32) / 256, 256>>>(kv, fcos, fsin);
    // 9. flash attention -> split bf16 attn
    mla_flash<<<dim3(S_LEN / FBM, H_N), 256, FLASH_SMEM>>>(q, kvup, kv, attnh, attnl);
    // 10. out = attn @ wo^T + b         [2048,2048]
    gemm_mma<<<dim3(D_DIM / 128, S_LEN / 128), 256, GM_SMEM>>>(
        attnh, attnl, woh, wol, wo_b, out, D_DIM, ATTN_N);
}

// round 4
// speedup vs baseline: 2.4083x; 1.4995x over previous
#include <cuda_runtime.h>
#include <cuda_bf16.h>
#include <cstdint>
#include <math.h>

// ---------------- problem constants ----------------
#define S_LEN   2048
#define D_DIM   2048
#define H_N     16
#define NOPE_D  128
#define ROPE_D  64
#define QK_D    192
#define VH_D    128
#define QLORA   1536
#define KVLORA  512
#define KVD     576
#define QUP_N   (H_N*QK_D)            // 3072
#define KVUP_N  (H_N*(NOPE_D+VH_D))   // 4096
#define ATTN_N  (H_N*VH_D)            // 2048

typedef __nv_bfloat16 bf16;

// ---------------- scratch ----------------
__device__ float g_qdown[S_LEN*QLORA];
__device__ float g_q    [S_LEN*QUP_N];
__device__ float g_kv   [S_LEN*KVD];
__device__ float g_kvup [S_LEN*KVUP_N];

__device__ bf16 g_xh[S_LEN*D_DIM],      g_xl[S_LEN*D_DIM];
__device__ bf16 g_qdnh[S_LEN*QLORA],    g_qdnl[S_LEN*QLORA];
__device__ bf16 g_kvnh[S_LEN*KVLORA],   g_kvnl[S_LEN*KVLORA];
__device__ bf16 g_attnh[S_LEN*ATTN_N],  g_attnl[S_LEN*ATTN_N];

__device__ bf16 g_qfh[S_LEN*QUP_N],     g_qfl[S_LEN*QUP_N];
__device__ bf16 g_kfh[S_LEN*QUP_N],     g_kfl[S_LEN*QUP_N];
__device__ bf16 g_vfh[S_LEN*ATTN_N],    g_vfl[S_LEN*ATTN_N];

__device__ bf16 g_wqdh[QLORA*D_DIM],    g_wqdl[QLORA*D_DIM];
__device__ bf16 g_wkvdh[KVD*D_DIM],     g_wkvdl[KVD*D_DIM];
__device__ bf16 g_wquh[QUP_N*QLORA],    g_wqul[QUP_N*QLORA];
__device__ bf16 g_wkvuh[KVUP_N*KVLORA], g_wkvul[KVUP_N*KVLORA];
__device__ bf16 g_woh[D_DIM*ATTN_N],    g_wol[D_DIM*ATTN_N];

// ---------------- PTX helpers (sm_80+ PTX only; compute_103-safe) ----------------
__device__ __forceinline__ uint32_t smem_u32(const void* p) {
    uint32_t a;
    asm("{ .reg .u64 t; cvta.to.shared.u64 t, %1; cvt.u32.u64 %0, t; }" : "=r"(a) : "l"(p));
    return a;
}

#define CP_ASYNC16(dst, src, sz) \
    asm volatile("cp.async.cg.shared.global [%0], [%1], 16, %2;" \
        :: "r"(dst), "l"(src), "r"(sz) : "memory")
#define CP_COMMIT()  asm volatile("cp.async.commit_group;" ::: "memory")
#define CP_WAIT(n)   asm volatile("cp.async.wait_group %0;" :: "n"(n) : "memory")

__device__ __forceinline__ void ldsm4(uint32_t addr, uint32_t* f) {
    asm volatile("ldmatrix.sync.aligned.m8n8.x4.shared.b16 {%0,%1,%2,%3}, [%4];"
        : "=r"(f[0]), "=r"(f[1]), "=r"(f[2]), "=r"(f[3]) : "r"(addr));
}
__device__ __forceinline__ void ldsm4t(uint32_t addr, uint32_t* f) {
    asm volatile("ldmatrix.sync.aligned.m8n8.x4.trans.shared.b16 {%0,%1,%2,%3}, [%4];"
        : "=r"(f[0]), "=r"(f[1]), "=r"(f[2]), "=r"(f[3]) : "r"(addr));
}

#define MMA16816(d, a, b0, b1) \
    asm volatile("mma.sync.aligned.m16n8k16.row.col.f32.bf16.bf16.f32 " \
        "{%0,%1,%2,%3}, {%4,%5,%6,%7}, {%8,%9}, {%0,%1,%2,%3};" \
        : "+f"((d)[0]), "+f"((d)[1]), "+f"((d)[2]), "+f"((d)[3]) \
        : "r"((a)[0]), "r"((a)[1]), "r"((a)[2]), "r"((a)[3]), "r"(b0), "r"(b1))

__device__ __forceinline__ uint32_t off16(int r, int c) {
    return (uint32_t)(r * 4 + ((((r >> 1) & 3) ^ c)));
}
__device__ __forceinline__ uint32_t pack_bf2(float a, float b) {
    __nv_bfloat162 t = __floats2bfloat162_rn(a, b);
    return *(uint32_t*)&t;
}
__device__ __forceinline__ void split2(float a, float b, uint32_t& h, uint32_t& l) {
    bf16 ah = __float2bfloat16(a), bh = __float2bfloat16(b);
    float ar = a - __bfloat162float(ah), br = b - __bfloat162float(bh);
    h = pack_bf2(__bfloat162float(ah), __bfloat162float(bh));
    l = pack_bf2(ar, br);
}

// ---------------- split f32 -> bf16 hi/lo ----------------
__global__ void split_f32(const float* __restrict__ x, bf16* __restrict__ h,
                          bf16* __restrict__ l, int n4)
{
    int i = blockIdx.x * blockDim.x + threadIdx.x;
    if (i >= n4) return;
    float4 v = ((const float4*)x)[i];
    bf16 h0 = __float2bfloat16(v.x), h1 = __float2bfloat16(v.y);
    bf16 h2 = __float2bfloat16(v.z), h3 = __float2bfloat16(v.w);
    bf16 l0 = __float2bfloat16(v.x - __bfloat162float(h0));
    bf16 l1 = __float2bfloat16(v.y - __bfloat162float(h1));
    bf16 l2 = __float2bfloat16(v.z - __bfloat162float(h2));
    bf16 l3 = __float2bfloat16(v.w - __bfloat162float(h3));
    bf16 hh[4] = {h0, h1, h2, h3};
    bf16 ll[4] = {l0, l1, l2, l3};
    ((uint2*)h)[i] = *(uint2*)hh;
    ((uint2*)l)[i] = *(uint2*)ll;
}

// ---------------- pack K (nope from kvup + rope from kv) and V ----------------
__global__ void pack_k(const float* __restrict__ kvup, const float* __restrict__ kv,
                       bf16* __restrict__ kh, bf16* __restrict__ kl)
{
    int i = blockIdx.x * blockDim.x + threadIdx.x;   // S*H*24
    int c = i % 24;
    int h = (i / 24) & (H_N - 1);
    int s = i / (24 * H_N);
    int d = c * 8;
    const float* src = (d < 128)
        ? kvup + (size_t)s * KVUP_N + h * 256 + d
        : kv   + (size_t)s * KVD + KVLORA + (d - 128);
    float4 v0 = *(const float4*)src;
    float4 v1 = *(const float4*)(src + 4);
    float v[8] = {v0.x, v0.y, v0.z, v0.w, v1.x, v1.y, v1.z, v1.w};
    bf16 hh[8], ll[8];
#pragma unroll
    for (int j = 0; j < 8; j++) {
        hh[j] = __float2bfloat16(v[j]);
        ll[j] = __float2bfloat16(v[j] - __bfloat162float(hh[j]));
    }
    size_t o = ((size_t)s * H_N + h) * QK_D + d;
    *(uint4*)(kh + o) = *(uint4*)hh;
    *(uint4*)(kl + o) = *(uint4*)ll;
}

__global__ void pack_v(const float* __restrict__ kvup,
                       bf16* __restrict__ vh, bf16* __restrict__ vl)
{
    int i = blockIdx.x * blockDim.x + threadIdx.x;   // S*H*16
    int c = i & 15;
    int h = (i >> 4) & (H_N - 1);
    int s = i >> 8;
    int d = c * 8;
    const float* src = kvup + (size_t)s * KVUP_N + h * 256 + 128 + d;
    float4 v0 = *(const float4*)src;
    float4 v1 = *(const float4*)(src + 4);
    float v[8] = {v0.x, v0.y, v0.z, v0.w, v1.x, v1.y, v1.z, v1.w};
    bf16 hh[8], ll[8];
#pragma unroll
    for (int j = 0; j < 8; j++) {
        hh[j] = __float2bfloat16(v[j]);
        ll[j] = __float2bfloat16(v[j] - __bfloat162float(hh[j]));
    }
    size_t o = ((size_t)s * H_N + h) * VH_D + d;
    *(uint4*)(vh + o) = *(uint4*)hh;
    *(uint4*)(vl + o) = *(uint4*)ll;
}

// ---------------- HMMA split-bf16 NT GEMM (unchanged from R3) ----------------
#define GM_SMEM (2*4*8192)

__global__ void __launch_bounds__(256) gemm_mma(
    const bf16* __restrict__ Ah, const bf16* __restrict__ Al,
    const bf16* __restrict__ Bh, const bf16* __restrict__ Bl,
    const float* __restrict__ bias, float* __restrict__ C,
    int N, int K)
{
    extern __shared__ __align__(1024) char sm[];
    const uint32_t smb = smem_u32(sm);

    const int tid = threadIdx.x;
    const int lane = tid & 31;
    const int wid = tid >> 5;
    const int warp_m = wid & 1;
    const int warp_n = wid >> 1;
    const int brow = blockIdx.y * 128;
    const int bcol = blockIdx.x * 128;

    const int r0g = tid >> 2;
    const int c0g = tid & 3;

    uint32_t aoff[4][2], boff[2][2];
#pragma unroll
    for (int mt = 0; mt < 4; mt++)
#pragma unroll
        for (int ks = 0; ks < 2; ks++) {
            int rr = warp_m * 64 + mt * 16 + (lane & 15);
            int cc = ks * 2 + (lane >> 4);
            aoff[mt][ks] = off16(rr, cc) * 16;
        }
#pragma unroll
    for (int g = 0; g < 2; g++)
#pragma unroll
        for (int ks = 0; ks < 2; ks++) {
            int rr = warp_n * 32 + g * 16 + (lane & 15);
            int cc = ks * 2 + (lane >> 4);
            boff[g][ks] = off16(rr, cc) * 16;
        }

    float acc[4][4][4];
#pragma unroll
    for (int i = 0; i < 4; i++)
#pragma unroll
        for (int j = 0; j < 4; j++)
#pragma unroll
            for (int k = 0; k < 4; k++) acc[i][j][k] = 0.f;

    const int KT = K >> 5;

    auto load_stage = [&](int s, int k0) {
        uint32_t base = smb + s * 32768;
#pragma unroll
        for (int it = 0; it < 2; it++) {
            int r = r0g + it * 64;
            int c = c0g;
            uint32_t doff = off16(r, c) * 16;
            size_t ga = (size_t)(brow + r) * K + k0 + c * 8;
            CP_ASYNC16(base + doff,         Ah + ga, 16);
            CP_ASYNC16(base + 8192 + doff,  Al + ga, 16);
            int gr = bcol + r;
            int ok = (gr < N) ? 16 : 0;
            size_t gb = (size_t)(ok ? gr : 0) * K + k0 + c * 8;
            CP_ASYNC16(base + 16384 + doff, Bh + gb, ok);
            CP_ASYNC16(base + 24576 + doff, Bl + gb, ok);
        }
        CP_COMMIT();
    };

    load_stage(0, 0);

    int buf = 0;
    for (int kt = 0; kt < KT; kt++) {
        if (kt + 1 < KT) {
            load_stage(buf ^ 1, (kt + 1) * 32);
            CP_WAIT(1);
        } else {
            CP_WAIT(0);
        }
        __syncthreads();

        uint32_t st = smb + buf * 32768;
#pragma unroll
        for (int pass = 0; pass < 3; pass++) {
            uint32_t aBase = st + (pass == 2 ? 8192 : 0);
            uint32_t bBase = st + (pass == 1 ? 24576 : 16384);
            uint32_t af[4][2][4], bfr[2][2][4];
#pragma unroll
            for (int mt = 0; mt < 4; mt++)
#pragma unroll
                for (int ks = 0; ks < 2; ks++)
                    ldsm4(aBase + aoff[mt][ks], af[mt][ks]);
#pragma unroll
            for (int g = 0; g < 2; g++)
#pragma unroll
                for (int ks = 0; ks < 2; ks++)
                    ldsm4(bBase + boff[g][ks], bfr[g][ks]);
#pragma unroll
            for (int mt = 0; mt < 4; mt++)
#pragma unroll
                for (int nt = 0; nt < 4; nt++) {
                    int g = nt >> 1, hf = nt & 1;
#pragma unroll
                    for (int ks = 0; ks < 2; ks++)
                        MMA16816(acc[mt][nt], af[mt][ks],
                                 bfr[g][ks][hf], bfr[g][ks][hf + 2]);
                }
        }
        __syncthreads();
        buf ^= 1;
    }

#pragma unroll
    for (int mt = 0; mt < 4; mt++) {
#pragma unroll
        for (int nt = 0; nt < 4; nt++) {
            int row = brow + warp_m * 64 + mt * 16 + (lane >> 2);
            int col = bcol + warp_n * 32 + nt * 8 + (lane & 3) * 2;
            if (col < N) {
                float b0 = bias[col], b1 = bias[col + 1];
                float2 v0 = make_float2(acc[mt][nt][0] + b0, acc[mt][nt][1] + b1);
                float2 v1 = make_float2(acc[mt][nt][2] + b0, acc[mt][nt][3] + b1);
                *(float2*)(C + (size_t)row * N + col) = v0;
                *(float2*)(C + (size_t)(row + 8) * N + col) = v1;
            }
        }
    }
}

// ---------------- RMSNorm -> split bf16 hi/lo ----------------
__global__ void __launch_bounds__(256) mla_rmsnorm_split(
    const float* __restrict__ X, int ldx, const float* __restrict__ w,
    bf16* __restrict__ Yh, bf16* __restrict__ Yl, int L)
{
    const int row = blockIdx.x;
    const float* x = X + (size_t)row * ldx;
    float ss = 0.f;
    for (int c = threadIdx.x; c < L; c += blockDim.x) {
        float v = x[c];
        ss = fmaf(v, v, ss);
    }
#pragma unroll
    for (int o = 16; o; o >>= 1) ss += __shfl_xor_sync(0xffffffffu, ss, o);
    __shared__ float red[8];
    __shared__ float s_inv;
    if ((threadIdx.x & 31) == 0) red[threadIdx.x >> 5] = ss;
    __syncthreads();
    if (threadIdx.x == 0) {
        float t = 0.f;
#pragma unroll
        for (int i = 0; i < 8; i++) t += red[i];
        s_inv = rsqrtf(t / (float)L + 1e-6f);
    }
    __syncthreads();
    float inv = s_inv;
    for (int c = threadIdx.x; c < L; c += blockDim.x) {
        float val = w[c] * (x[c] * inv);
        bf16 hi = __float2bfloat16(val);
        bf16 lo = __float2bfloat16(val - __bfloat162float(hi));
        Yh[(size_t)row * L + c] = hi;
        Yl[(size_t)row * L + c] = lo;
    }
}

// ---------------- RoPE ----------------
__global__ void mla_rope_q(float* __restrict__ q, const float* __restrict__ fc,
                           const float* __restrict__ fs)
{
    int idx = blockIdx.x * blockDim.x + threadIdx.x;
    int i = idx & 31;
    int h = (idx >> 5) & (H_N - 1);
    int s = idx >> 9;
    float c = fc[s * 32 + i], sn = fs[s * 32 + i];
    float* p = q + (size_t)s * QUP_N + h * QK_D + NOPE_D + 2 * i;
    float x0 = p[0], x1 = p[1];
    p[0] = x0 * c - x1 * sn;
    p[1] = x0 * sn + x1 * c;
}
__global__ void mla_rope_k(float* __restrict__ kv, const float* __restrict__ fc,
                           const float* __restrict__ fs)
{
    int idx = blockIdx.x * blockDim.x + threadIdx.x;
    int i = idx & 31;
    int s = idx >> 5;
    float c = fc[s * 32 + i], sn = fs[s * 32 + i];
    float* p = kv + (size_t)s * KVD + KVLORA + 2 * i;
    float x0 = p[0], x1 = p[1];
    p[0] = x0 * c - x1 * sn;
    p[1] = x0 * sn + x1 * c;
}

// ---------------- HMMA flash attention (causal, split-bf16) ----------------
// CTA: 128 q-rows x 1 head. 8 warps, each m16. Streams 64-key blocks.
// Q/K rows padded 192->200 bf16 (400B), V rows 128->136 (272B): stride%128==16.
#define FQ 128
#define FK 64
#define QSTRB 400
#define VSTRB 272
#define SQH 0
#define SQL 51200
#define SKH 102400
#define SKL 128000
#define SVH 153600
#define SVL 171008
#define FLASH_SMEM 188416

__global__ void __launch_bounds__(256, 1) mla_flash_mma(
    const bf16* __restrict__ Qh, const bf16* __restrict__ Ql,
    const bf16* __restrict__ Kh, const bf16* __restrict__ Kl,
    const bf16* __restrict__ Vh, const bf16* __restrict__ Vl,
    bf16* __restrict__ Oh, bf16* __restrict__ Ol)
{
    extern __shared__ __align__(1024) char fs[];
    const uint32_t smb = smem_u32(fs);

    const int h = blockIdx.y;
    const int qb = blockIdx.x;
    const int qbase = qb * FQ;
    const int tid = threadIdx.x;
    const int lane = tid & 31;
    const int wid = tid >> 5;
    const int row_min = qbase + wid * 16;

    // ---- load Q tile (hi+lo) via cp.async ----
    for (int i = tid; i < FQ * 24; i += 256) {
        int r = i / 24, c = i % 24;
        size_t go = ((size_t)(qbase + r) * H_N + h) * QK_D + c * 8;
        uint32_t so = (uint32_t)(r * QSTRB + c * 16);
        CP_ASYNC16(smb + SQH + so, Qh + go, 16);
        CP_ASYNC16(smb + SQL + so, Ql + go, 16);
    }
    CP_COMMIT();

    // per-thread fragment base addresses
    const uint32_t qfb = smb + SQH + (uint32_t)((wid * 16 + (lane & 15)) * QSTRB + (lane >> 4) * 16);
    const uint32_t kfb = smb + SKH + (uint32_t)((lane & 15) * QSTRB + (lane >> 4) * 16);
    const uint32_t vfb = smb + SVH + (uint32_t)((lane & 15) * VSTRB + (lane >> 4) * 16);

    float o[16][4];
#pragma unroll
    for (int g = 0; g < 16; g++)
#pragma unroll
        for (int j = 0; j < 4; j++) o[g][j] = 0.f;
    float m0 = -1e30f, m1 = -1e30f, l0 = 0.f, l1 = 0.f;
    const float scale = 0.07216878364870322f;

    const int nkb = 2 * qb + 2;
    for (int kb = 0; kb < nkb; kb++) {
        const int kbase = kb * FK;

        // ---- load K/V block (hi+lo) ----
        for (int i = tid; i < FK * 24; i += 256) {
            int r = i / 24, c = i % 24;
            size_t go = ((size_t)(kbase + r) * H_N + h) * QK_D + c * 8;
            uint32_t so = (uint32_t)(r * QSTRB + c * 16);
            CP_ASYNC16(smb + SKH + so, Kh + go, 16);
            CP_ASYNC16(smb + SKL + so, Kl + go, 16);
        }
        for (int i = tid; i < FK * 16; i += 256) {
            int r = i >> 4, c = i & 15;
            size_t go = ((size_t)(kbase + r) * H_N + h) * VH_D + c * 8;
            uint32_t so = (uint32_t)(r * VSTRB + c * 16);
            CP_ASYNC16(smb + SVH + so, Vh + go, 16);
            CP_ASYNC16(smb + SVL + so, Vl + go, 16);
        }
        CP_COMMIT();
        CP_WAIT(0);
        __syncthreads();

        if (kbase <= row_min + 15) {   // warp has at least one visible key
            // ---- S = Q K^T (3 split passes) ----
            float c[8][4];
#pragma unroll
            for (int g = 0; g < 8; g++)
#pragma unroll
                for (int j = 0; j < 4; j++) c[g][j] = 0.f;

#pragma unroll
            for (int ks = 0; ks < 12; ks++) {
                uint32_t ah[4], al[4];
                ldsm4(qfb + ks * 32, ah);
                ldsm4(qfb + (SQL - SQH) + ks * 32, al);
#pragma unroll
                for (int gg = 0; gg < 4; gg++) {
                    uint32_t bh[4], bl[4];
                    ldsm4(kfb + gg * (16 * QSTRB) + ks * 32, bh);
                    ldsm4(kfb + (SKL - SKH) + gg * (16 * QSTRB) + ks * 32, bl);
                    MMA16816(c[2 * gg],     ah, bh[0], bh[2]);
                    MMA16816(c[2 * gg + 1], ah, bh[1], bh[3]);
                    MMA16816(c[2 * gg],     ah, bl[0], bl[2]);
                    MMA16816(c[2 * gg + 1], ah, bl[1], bl[3]);
                    MMA16816(c[2 * gg],     al, bh[0], bh[2]);
                    MMA16816(c[2 * gg + 1], al, bh[1], bh[3]);
                }
            }

            // ---- scale + causal mask ----
            const int row0 = row_min + (lane >> 2);
            const bool needmask = (kbase + FK - 1 > row_min);
#pragma unroll
            for (int g = 0; g < 8; g++) {
                int col = kbase + g * 8 + (lane & 3) * 2;
#pragma unroll
                for (int j = 0; j < 4; j++) {
                    float v = c[g][j] * scale;
                    if (needmask) {
                        int cc = col + (j & 1);
                        int rr = row0 + ((j >> 1) << 3);
                        if (cc > rr) v = -1e30f;
                    }
                    c[g][j] = v;
                }
            }

            // ---- online softmax (rows: row0, row0+8; quad lanes share a row) ----
            float mx0 = -1e30f, mx1 = -1e30f;
#pragma unroll
            for (int g = 0; g < 8; g++) {
                mx0 = fmaxf(mx0, fmaxf(c[g][0], c[g][1]));
                mx1 = fmaxf(mx1, fmaxf(c[g][2], c[g][3]));
            }
#pragma unroll
            for (int off = 1; off < 4; off <<= 1) {
                mx0 = fmaxf(mx0, __shfl_xor_sync(0xffffffffu, mx0, off));
                mx1 = fmaxf(mx1, __shfl_xor_sync(0xffffffffu, mx1, off));
            }
            float mn0 = fmaxf(m0, mx0), mn1 = fmaxf(m1, mx1);
            float al0 = __expf(m0 - mn0), al1 = __expf(m1 - mn1);
            float rs0 = 0.f, rs1 = 0.f;
#pragma unroll
            for (int g = 0; g < 8; g++) {
                c[g][0] = __expf(c[g][0] - mn0); rs0 += c[g][0];
                c[g][1] = __expf(c[g][1] - mn0); rs0 += c[g][1];
                c[g][2] = __expf(c[g][2] - mn1); rs1 += c[g][2];
                c[g][3] = __expf(c[g][3] - mn1); rs1 += c[g][3];
            }
#pragma unroll
            for (int off = 1; off < 4; off <<= 1) {
                rs0 += __shfl_xor_sync(0xffffffffu, rs0, off);
                rs1 += __shfl_xor_sync(0xffffffffu, rs1, off);
            }
            l0 = l0 * al0 + rs0; l1 = l1 * al1 + rs1;
            m0 = mn0; m1 = mn1;
#pragma unroll
            for (int g = 0; g < 16; g++) {
                o[g][0] *= al0; o[g][1] *= al0;
                o[g][2] *= al1; o[g][3] *= al1;
            }

            // ---- O += P V (P in registers, split hi/lo; 3 passes) ----
#pragma unroll
            for (int kc = 0; kc < 4; kc++) {
                uint32_t aph[4], apl[4];
                split2(c[2 * kc][0],     c[2 * kc][1],     aph[0], apl[0]);
                split2(c[2 * kc][2],     c[2 * kc][3],     aph[1], apl[1]);
                split2(c[2 * kc + 1][0], c[2 * kc + 1][1], aph[2], apl[2]);
                split2(c[2 * kc + 1][2], c[2 * kc + 1][3], aph[3], apl[3]);
#pragma unroll
                for (int ng = 0; ng < 8; ng++) {
                    uint32_t vh4[4], vl4[4];
                    ldsm4t(vfb + kc * (16 * VSTRB) + ng * 32, vh4);
                    ldsm4t(vfb + (SVL - SVH) + kc * (16 * VSTRB) + ng * 32, vl4);
                    MMA16816(o[2 * ng],     aph, vh4[0], vh4[1]);
                    MMA16816(o[2 * ng + 1], aph, vh4[2], vh4[3]);
                    MMA16816(o[2 * ng],     aph, vl4[0], vl4[1]);
                    MMA16816(o[2 * ng + 1], aph, vl4[2], vl4[3]);
                    MMA16816(o[2 * ng],     apl, vh4[0], vh4[1]);
                    MMA16816(o[2 * ng + 1], apl, vh4[2], vh4[3]);
                }
            }
        }
        __syncthreads();
    }

    // ---- write O (split bf16 for the wo GEMM) ----
    float inv0 = 1.0f / l0, inv1 = 1.0f / l1;
    int row0 = row_min + (lane >> 2);
#pragma unroll
    for (int g = 0; g < 16; g++) {
        int col = h * VH_D + g * 8 + (lane & 3) * 2;
        uint32_t hh, ll;
        split2(o[g][0] * inv0, o[g][1] * inv0, hh, ll);
        *(uint32_t*)(Oh + (size_t)row0 * ATTN_N + col) = hh;
        *(uint32_t*)(Ol + (size_t)row0 * ATTN_N + col) = ll;
        split2(o[g][2] * inv1, o[g][3] * inv1, hh, ll);
        *(uint32_t*)(Oh + (size_t)(row0 + 8) * ATTN_N + col) = hh;
        *(uint32_t*)(Ol + (size_t)(row0 + 8) * ATTN_N + col) = ll;
    }
}

// ---------------- launch ----------------
static inline void split_launch(const float* src, bf16* h, bf16* l, int n) {
    int n4 = n / 4;
    split_f32<<<(n4 + 255) / 256, 256>>>(src, h, l, n4);
}

extern "C" void kernel_launch(void* const* d_in, const int* in_sizes, int n_in,
                              void* d_out, int out_size)
{
    const float* x          = (const float*)d_in[0];
    const float* fcos       = (const float*)d_in[2];
    const float* fsin       = (const float*)d_in[3];
    const float* wq_down_w  = (const float*)d_in[5];
    const float* wq_down_b  = (const float*)d_in[6];
    const float* q_norm_w   = (const float*)d_in[7];
    const float* wq_up_w    = (const float*)d_in[8];
    const float* wq_up_b    = (const float*)d_in[9];
    const float* wkv_down_w = (const float*)d_in[10];
    const float* wkv_down_b = (const float*)d_in[11];
    const float* kv_norm_w  = (const float*)d_in[12];
    const float* wkv_up_w   = (const float*)d_in[13];
    const float* wkv_up_b   = (const float*)d_in[14];
    const float* wo_w       = (const float*)d_in[15];
    const float* wo_b       = (const float*)d_in[16];
    float* out = (float*)d_out;

    float *qdown, *q, *kv, *kvup;
    bf16 *xh, *xl, *qdnh, *qdnl, *kvnh, *kvnl, *attnh, *attnl;
    bf16 *qfh, *qfl, *kfh, *kfl, *vfh, *vfl;
    bf16 *wqdh, *wqdl, *wkvdh, *wkvdl, *wquh, *wqul, *wkvuh, *wkvul, *woh, *wol;
    cudaGetSymbolAddress((void**)&qdown, g_qdown);
    cudaGetSymbolAddress((void**)&q,     g_q);
    cudaGetSymbolAddress((void**)&kv,    g_kv);
    cudaGetSymbolAddress((void**)&kvup,  g_kvup);
    cudaGetSymbolAddress((void**)&xh, g_xh);       cudaGetSymbolAddress((void**)&xl, g_xl);
    cudaGetSymbolAddress((void**)&qdnh, g_qdnh);   cudaGetSymbolAddress((void**)&qdnl, g_qdnl);
    cudaGetSymbolAddress((void**)&kvnh, g_kvnh);   cudaGetSymbolAddress((void**)&kvnl, g_kvnl);
    cudaGetSymbolAddress((void**)&attnh, g_attnh); cudaGetSymbolAddress((void**)&attnl, g_attnl);
    cudaGetSymbolAddress((void**)&qfh, g_qfh);     cudaGetSymbolAddress((void**)&qfl, g_qfl);
    cudaGetSymbolAddress((void**)&kfh, g_kfh);     cudaGetSymbolAddress((void**)&kfl, g_kfl);
    cudaGetSymbolAddress((void**)&vfh, g_vfh);     cudaGetSymbolAddress((void**)&vfl, g_vfl);
    cudaGetSymbolAddress((void**)&wqdh, g_wqdh);   cudaGetSymbolAddress((void**)&wqdl, g_wqdl);
    cudaGetSymbolAddress((void**)&wkvdh, g_wkvdh); cudaGetSymbolAddress((void**)&wkvdl, g_wkvdl);
    cudaGetSymbolAddress((void**)&wquh, g_wquh);   cudaGetSymbolAddress((void**)&wqul, g_wqul);
    cudaGetSymbolAddress((void**)&wkvuh, g_wkvuh); cudaGetSymbolAddress((void**)&wkvul, g_wkvul);
    cudaGetSymbolAddress((void**)&woh, g_woh);     cudaGetSymbolAddress((void**)&wol, g_wol);

    cudaFuncSetAttribute(gemm_mma, cudaFuncAttributeMaxDynamicSharedMemorySize, GM_SMEM);
    cudaFuncSetAttribute(mla_flash_mma, cudaFuncAttributeMaxDynamicSharedMemorySize, FLASH_SMEM);

    // splits
    split_launch(x,          xh,    xl,    S_LEN * D_DIM);
    split_launch(wq_down_w,  wqdh,  wqdl,  QLORA * D_DIM);
    split_launch(wkv_down_w, wkvdh, wkvdl, KVD * D_DIM);
    split_launch(wq_up_w,    wquh,  wqul,  QUP_N * QLORA);
    split_launch(wkv_up_w,   wkvuh, wkvul, KVUP_N * KVLORA);
    split_launch(wo_w,       woh,   wol,   D_DIM * ATTN_N);

    // projections
    gemm_mma<<<dim3(QLORA / 128, S_LEN / 128), 256, GM_SMEM>>>(
        xh, xl, wqdh, wqdl, wq_down_b, qdown, QLORA, D_DIM);
    gemm_mma<<<dim3((KVD + 127) / 128, S_LEN / 128), 256, GM_SMEM>>>(
        xh, xl, wkvdh, wkvdl, wkv_down_b, kv, KVD, D_DIM);
    mla_rmsnorm_split<<<S_LEN, 256>>>(qdown, QLORA, q_norm_w, qdnh, qdnl, QLORA);
    mla_rmsnorm_split<<<S_LEN, 256>>>(kv, KVD, kv_norm_w, kvnh, kvnl, KVLORA);
    gemm_mma<<<dim3(QUP_N / 128, S_LEN / 128), 256, GM_SMEM>>>(
        qdnh, qdnl, wquh, wqul, wq_up_b, q, QUP_N, QLORA);
    gemm_mma<<<dim3(KVUP_N / 128, S_LEN / 128), 256, GM_SMEM>>>(
        kvnh, kvnl, wkvuh, wkvul, wkv_up_b, kvup, KVUP_N, KVLORA);

    // rope + pack to bf16 hi/lo
    mla_rope_q<<<(S_LEN * H_N * 32) / 256, 256>>>(q, fcos, fsin);
    mla_rope_k<<<(S_LEN * 32) / 256, 256>>>(kv, fcos, fsin);
    split_launch(q, qfh, qfl, S_LEN * QUP_N);
    pack_k<<<(S_LEN * H_N * 24) / 256, 256>>>(kvup, kv, kfh, kfl);
    pack_v<<<(S_LEN * H_N * 16) / 256, 256>>>(kvup, vfh, vfl);

    // HMMA flash attention
    mla_flash_mma<<<dim3(S_LEN / FQ, H_N), 256, FLASH_SMEM>>>(
        qfh, qfl, kfh, kfl, vfh, vfl, attnh, attnl);

    // output projection
    gemm_mma<<<dim3(D_DIM / 128, S_LEN / 128), 256, GM_SMEM>>>(
        attnh, attnl, woh, wol, wo_b, out, D_DIM, ATTN_N);
}

// round 5
// speedup vs baseline: 2.4211x; 1.0053x over previous
#include <cuda_runtime.h>
#include <cuda_bf16.h>
#include <cstdint>
#include <math.h>

// ---------------- problem constants ----------------
#define S_LEN   2048
#define D_DIM   2048
#define H_N     16
#define NOPE_D  128
#define ROPE_D  64
#define QK_D    192
#define VH_D    128
#define QLORA   1536
#define KVLORA  512
#define KVD     576
#define QUP_N   (H_N*QK_D)            // 3072
#define KVUP_N  (H_N*(NOPE_D+VH_D))   // 4096
#define ATTN_N  (H_N*VH_D)            // 2048

typedef __nv_bfloat16 bf16;

// ---------------- scratch ----------------
__device__ float g_qdown[S_LEN*QLORA];
__device__ float g_q    [S_LEN*QUP_N];
__device__ float g_kv   [S_LEN*KVD];
__device__ float g_kvup [S_LEN*KVUP_N];

__device__ bf16 g_xh[S_LEN*D_DIM],      g_xl[S_LEN*D_DIM];
__device__ bf16 g_qdnh[S_LEN*QLORA],    g_qdnl[S_LEN*QLORA];
__device__ bf16 g_kvnh[S_LEN*KVLORA],   g_kvnl[S_LEN*KVLORA];
__device__ bf16 g_attnh[S_LEN*ATTN_N],  g_attnl[S_LEN*ATTN_N];

__device__ bf16 g_qfh[S_LEN*QUP_N],     g_qfl[S_LEN*QUP_N];
__device__ bf16 g_kfh[S_LEN*QUP_N],     g_kfl[S_LEN*QUP_N];
__device__ bf16 g_vfh[S_LEN*ATTN_N],    g_vfl[S_LEN*ATTN_N];

__device__ bf16 g_wqdh[QLORA*D_DIM],    g_wqdl[QLORA*D_DIM];
__device__ bf16 g_wkvdh[KVD*D_DIM],     g_wkvdl[KVD*D_DIM];
__device__ bf16 g_wquh[QUP_N*QLORA],    g_wqul[QUP_N*QLORA];
__device__ bf16 g_wkvuh[KVUP_N*KVLORA], g_wkvul[KVUP_N*KVLORA];
__device__ bf16 g_woh[D_DIM*ATTN_N],    g_wol[D_DIM*ATTN_N];

// ---------------- PTX helpers (sm_80+ PTX only; compute_103-safe) ----------------
__device__ __forceinline__ uint32_t smem_u32(const void* p) {
    uint32_t a;
    asm("{ .reg .u64 t; cvta.to.shared.u64 t, %1; cvt.u32.u64 %0, t; }" : "=r"(a) : "l"(p));
    return a;
}

#define CP_ASYNC16(dst, src, sz) \
    asm volatile("cp.async.cg.shared.global [%0], [%1], 16, %2;" \
        :: "r"(dst), "l"(src), "r"(sz) : "memory")
#define CP_COMMIT()  asm volatile("cp.async.commit_group;" ::: "memory")
#define CP_WAIT(n)   asm volatile("cp.async.wait_group %0;" :: "n"(n) : "memory")

__device__ __forceinline__ void ldsm4(uint32_t addr, uint32_t* f) {
    asm volatile("ldmatrix.sync.aligned.m8n8.x4.shared.b16 {%0,%1,%2,%3}, [%4];"
        : "=r"(f[0]), "=r"(f[1]), "=r"(f[2]), "=r"(f[3]) : "r"(addr));
}
__device__ __forceinline__ void ldsm4t(uint32_t addr, uint32_t* f) {
    asm volatile("ldmatrix.sync.aligned.m8n8.x4.trans.shared.b16 {%0,%1,%2,%3}, [%4];"
        : "=r"(f[0]), "=r"(f[1]), "=r"(f[2]), "=r"(f[3]) : "r"(addr));
}

#define MMA16816(d, a, b0, b1) \
    asm volatile("mma.sync.aligned.m16n8k16.row.col.f32.bf16.bf16.f32 " \
        "{%0,%1,%2,%3}, {%4,%5,%6,%7}, {%8,%9}, {%0,%1,%2,%3};" \
        : "+f"((d)[0]), "+f"((d)[1]), "+f"((d)[2]), "+f"((d)[3]) \
        : "r"((a)[0]), "r"((a)[1]), "r"((a)[2]), "r"((a)[3]), "r"(b0), "r"(b1))

__device__ __forceinline__ uint32_t off16(int r, int c) {
    return (uint32_t)(r * 4 + ((((r >> 1) & 3) ^ c)));
}
__device__ __forceinline__ uint32_t pack_bf2(float a, float b) {
    __nv_bfloat162 t = __floats2bfloat162_rn(a, b);
    return *(uint32_t*)&t;
}
__device__ __forceinline__ void split2(float a, float b, uint32_t& h, uint32_t& l) {
    bf16 ah = __float2bfloat16(a), bh = __float2bfloat16(b);
    float ar = a - __bfloat162float(ah), br = b - __bfloat162float(bh);
    h = pack_bf2(__bfloat162float(ah), __bfloat162float(bh));
    l = pack_bf2(ar, br);
}

// ---------------- split f32 -> bf16 hi/lo ----------------
__global__ void split_f32(const float* __restrict__ x, bf16* __restrict__ h,
                          bf16* __restrict__ l, int n4)
{
    int i = blockIdx.x * blockDim.x + threadIdx.x;
    if (i >= n4) return;
    float4 v = ((const float4*)x)[i];
    bf16 h0 = __float2bfloat16(v.x), h1 = __float2bfloat16(v.y);
    bf16 h2 = __float2bfloat16(v.z), h3 = __float2bfloat16(v.w);
    bf16 l0 = __float2bfloat16(v.x - __bfloat162float(h0));
    bf16 l1 = __float2bfloat16(v.y - __bfloat162float(h1));
    bf16 l2 = __float2bfloat16(v.z - __bfloat162float(h2));
    bf16 l3 = __float2bfloat16(v.w - __bfloat162float(h3));
    bf16 hh[4] = {h0, h1, h2, h3};
    bf16 ll[4] = {l0, l1, l2, l3};
    ((uint2*)h)[i] = *(uint2*)hh;
    ((uint2*)l)[i] = *(uint2*)ll;
}

// ---------------- fused rope + split for Q: f32 [S,H*192] -> bf16 hi/lo [S,H,192] ----------------
__global__ void rope_split_q(const float* __restrict__ q,
                             const float* __restrict__ fc, const float* __restrict__ fs,
                             bf16* __restrict__ qh, bf16* __restrict__ ql)
{
    int i = blockIdx.x * blockDim.x + threadIdx.x;   // S*H*24
    int c = i % 24;
    int h = (i / 24) & (H_N - 1);
    int s = i / (24 * H_N);
    int d = c * 8;
    const float* src = q + (size_t)s * QUP_N + h * QK_D + d;
    float4 v0 = *(const float4*)src;
    float4 v1 = *(const float4*)(src + 4);
    float v[8] = {v0.x, v0.y, v0.z, v0.w, v1.x, v1.y, v1.z, v1.w};
    if (d >= NOPE_D) {           // rope region: 4 pairs
        int p0 = (d - NOPE_D) >> 1;
#pragma unroll
        for (int j = 0; j < 4; j++) {
            float cc = fc[s * 32 + p0 + j], ss = fs[s * 32 + p0 + j];
            float x0 = v[2 * j], x1 = v[2 * j + 1];
            v[2 * j]     = x0 * cc - x1 * ss;
            v[2 * j + 1] = x0 * ss + x1 * cc;
        }
    }
    bf16 hh[8], ll[8];
#pragma unroll
    for (int j = 0; j < 8; j++) {
        hh[j] = __float2bfloat16(v[j]);
        ll[j] = __float2bfloat16(v[j] - __bfloat162float(hh[j]));
    }
    size_t o = ((size_t)s * H_N + h) * QK_D + d;
    *(uint4*)(qh + o) = *(uint4*)hh;
    *(uint4*)(ql + o) = *(uint4*)ll;
}

// ---------------- fused pack K (nope from kvup + rope'd pe from kv) ----------------
__global__ void pack_k(const float* __restrict__ kvup, const float* __restrict__ kv,
                       const float* __restrict__ fc, const float* __restrict__ fs,
                       bf16* __restrict__ kh, bf16* __restrict__ kl)
{
    int i = blockIdx.x * blockDim.x + threadIdx.x;   // S*H*24
    int c = i % 24;
    int h = (i / 24) & (H_N - 1);
    int s = i / (24 * H_N);
    int d = c * 8;
    float v[8];
    if (d < NOPE_D) {
        const float* src = kvup + (size_t)s * KVUP_N + h * 256 + d;
        float4 v0 = *(const float4*)src;
        float4 v1 = *(const float4*)(src + 4);
        v[0]=v0.x; v[1]=v0.y; v[2]=v0.z; v[3]=v0.w; v[4]=v1.x; v[5]=v1.y; v[6]=v1.z; v[7]=v1.w;
    } else {
        const float* src = kv + (size_t)s * KVD + KVLORA + (d - NOPE_D);
        float4 v0 = *(const float4*)src;
        float4 v1 = *(const float4*)(src + 4);
        v[0]=v0.x; v[1]=v0.y; v[2]=v0.z; v[3]=v0.w; v[4]=v1.x; v[5]=v1.y; v[6]=v1.z; v[7]=v1.w;
        int p0 = (d - NOPE_D) >> 1;
#pragma unroll
        for (int j = 0; j < 4; j++) {
            float cc = fc[s * 32 + p0 + j], ss = fs[s * 32 + p0 + j];
            float x0 = v[2 * j], x1 = v[2 * j + 1];
            v[2 * j]     = x0 * cc - x1 * ss;
            v[2 * j + 1] = x0 * ss + x1 * cc;
        }
    }
    bf16 hh[8], ll[8];
#pragma unroll
    for (int j = 0; j < 8; j++) {
        hh[j] = __float2bfloat16(v[j]);
        ll[j] = __float2bfloat16(v[j] - __bfloat162float(hh[j]));
    }
    size_t o = ((size_t)s * H_N + h) * QK_D + d;
    *(uint4*)(kh + o) = *(uint4*)hh;
    *(uint4*)(kl + o) = *(uint4*)ll;
}

__global__ void pack_v(const float* __restrict__ kvup,
                       bf16* __restrict__ vh, bf16* __restrict__ vl)
{
    int i = blockIdx.x * blockDim.x + threadIdx.x;   // S*H*16
    int c = i & 15;
    int h = (i >> 4) & (H_N - 1);
    int s = i >> 8;
    int d = c * 8;
    const float* src = kvup + (size_t)s * KVUP_N + h * 256 + 128 + d;
    float4 v0 = *(const float4*)src;
    float4 v1 = *(const float4*)(src + 4);
    float v[8] = {v0.x, v0.y, v0.z, v0.w, v1.x, v1.y, v1.z, v1.w};
    bf16 hh[8], ll[8];
#pragma unroll
    for (int j = 0; j < 8; j++) {
        hh[j] = __float2bfloat16(v[j]);
        ll[j] = __float2bfloat16(v[j] - __bfloat162float(hh[j]));
    }
    size_t o = ((size_t)s * H_N + h) * VH_D + d;
    *(uint4*)(vh + o) = *(uint4*)hh;
    *(uint4*)(vl + o) = *(uint4*)ll;
}

// ---------------- HMMA split-bf16 NT GEMM ----------------
// 3 passes ordered (Ah,Bh),(Ah,Bl),(Al,Bh): A-hi fragments reused across passes 0-1.
#define GM_SMEM (2*4*8192)

__global__ void __launch_bounds__(256) gemm_mma(
    const bf16* __restrict__ Ah, const bf16* __restrict__ Al,
    const bf16* __restrict__ Bh, const bf16* __restrict__ Bl,
    const float* __restrict__ bias, float* __restrict__ C,
    int N, int K)
{
    extern __shared__ __align__(1024) char sm[];
    const uint32_t smb = smem_u32(sm);

    const int tid = threadIdx.x;
    const int lane = tid & 31;
    const int wid = tid >> 5;
    const int warp_m = wid & 1;
    const int warp_n = wid >> 1;
    const int brow = blockIdx.y * 128;
    const int bcol = blockIdx.x * 128;

    const int r0g = tid >> 2;
    const int c0g = tid & 3;

    uint32_t aoff[4][2], boff[2][2];
#pragma unroll
    for (int mt = 0; mt < 4; mt++)
#pragma unroll
        for (int ks = 0; ks < 2; ks++) {
            int rr = warp_m * 64 + mt * 16 + (lane & 15);
            int cc = ks * 2 + (lane >> 4);
            aoff[mt][ks] = off16(rr, cc) * 16;
        }
#pragma unroll
    for (int g = 0; g < 2; g++)
#pragma unroll
        for (int ks = 0; ks < 2; ks++) {
            int rr = warp_n * 32 + g * 16 + (lane & 15);
            int cc = ks * 2 + (lane >> 4);
            boff[g][ks] = off16(rr, cc) * 16;
        }

    float acc[4][4][4];
#pragma unroll
    for (int i = 0; i < 4; i++)
#pragma unroll
        for (int j = 0; j < 4; j++)
#pragma unroll
            for (int k = 0; k < 4; k++) acc[i][j][k] = 0.f;

    const int KT = K >> 5;

    auto load_stage = [&](int s, int k0) {
        uint32_t base = smb + s * 32768;
#pragma unroll
        for (int it = 0; it < 2; it++) {
            int r = r0g + it * 64;
            int c = c0g;
            uint32_t doff = off16(r, c) * 16;
            size_t ga = (size_t)(brow + r) * K + k0 + c * 8;
            CP_ASYNC16(base + doff,         Ah + ga, 16);
            CP_ASYNC16(base + 8192 + doff,  Al + ga, 16);
            int gr = bcol + r;
            int ok = (gr < N) ? 16 : 0;
            size_t gb = (size_t)(ok ? gr : 0) * K + k0 + c * 8;
            CP_ASYNC16(base + 16384 + doff, Bh + gb, ok);
            CP_ASYNC16(base + 24576 + doff, Bl + gb, ok);
        }
        CP_COMMIT();
    };

    load_stage(0, 0);

    uint32_t af[4][2][4], bfr[2][2][4];

    auto mma_block = [&]() {
#pragma unroll
        for (int mt = 0; mt < 4; mt++)
#pragma unroll
            for (int nt = 0; nt < 4; nt++) {
                int g = nt >> 1, hf = nt & 1;
#pragma unroll
                for (int ks = 0; ks < 2; ks++)
                    MMA16816(acc[mt][nt], af[mt][ks],
                             bfr[g][ks][hf], bfr[g][ks][hf + 2]);
            }
    };

    int buf = 0;
    for (int kt = 0; kt < KT; kt++) {
        if (kt + 1 < KT) {
            load_stage(buf ^ 1, (kt + 1) * 32);
            CP_WAIT(1);
        } else {
            CP_WAIT(0);
        }
        __syncthreads();

        uint32_t st = smb + buf * 32768;

        // pass 0: A-hi x B-hi
#pragma unroll
        for (int mt = 0; mt < 4; mt++)
#pragma unroll
            for (int ks = 0; ks < 2; ks++)
                ldsm4(st + aoff[mt][ks], af[mt][ks]);
#pragma unroll
        for (int g = 0; g < 2; g++)
#pragma unroll
            for (int ks = 0; ks < 2; ks++)
                ldsm4(st + 16384 + boff[g][ks], bfr[g][ks]);
        mma_block();

        // pass 1: A-hi (reused) x B-lo
#pragma unroll
        for (int g = 0; g < 2; g++)
#pragma unroll
            for (int ks = 0; ks < 2; ks++)
                ldsm4(st + 24576 + boff[g][ks], bfr[g][ks]);
        mma_block();

        // pass 2: A-lo x B-hi
#pragma unroll
        for (int mt = 0; mt < 4; mt++)
#pragma unroll
            for (int ks = 0; ks < 2; ks++)
                ldsm4(st + 8192 + aoff[mt][ks], af[mt][ks]);
#pragma unroll
        for (int g = 0; g < 2; g++)
#pragma unroll
            for (int ks = 0; ks < 2; ks++)
                ldsm4(st + 16384 + boff[g][ks], bfr[g][ks]);
        mma_block();

        __syncthreads();
        buf ^= 1;
    }

#pragma unroll
    for (int mt = 0; mt < 4; mt++) {
#pragma unroll
        for (int nt = 0; nt < 4; nt++) {
            int row = brow + warp_m * 64 + mt * 16 + (lane >> 2);
            int col = bcol + warp_n * 32 + nt * 8 + (lane & 3) * 2;
            if (col < N) {
                float b0 = bias[col], b1 = bias[col + 1];
                float2 v0 = make_float2(acc[mt][nt][0] + b0, acc[mt][nt][1] + b1);
                float2 v1 = make_float2(acc[mt][nt][2] + b0, acc[mt][nt][3] + b1);
                *(float2*)(C + (size_t)row * N + col) = v0;
                *(float2*)(C + (size_t)(row + 8) * N + col) = v1;
            }
        }
    }
}

// ---------------- RMSNorm -> split bf16 hi/lo ----------------
__global__ void __launch_bounds__(256) mla_rmsnorm_split(
    const float* __restrict__ X, int ldx, const float* __restrict__ w,
    bf16* __restrict__ Yh, bf16* __restrict__ Yl, int L)
{
    const int row = blockIdx.x;
    const float* x = X + (size_t)row * ldx;
    float ss = 0.f;
    for (int c = threadIdx.x; c < L; c += blockDim.x) {
        float v = x[c];
        ss = fmaf(v, v, ss);
    }
#pragma unroll
    for (int o = 16; o; o >>= 1) ss += __shfl_xor_sync(0xffffffffu, ss, o);
    __shared__ float red[8];
    __shared__ float s_inv;
    if ((threadIdx.x & 31) == 0) red[threadIdx.x >> 5] = ss;
    __syncthreads();
    if (threadIdx.x == 0) {
        float t = 0.f;
#pragma unroll
        for (int i = 0; i < 8; i++) t += red[i];
        s_inv = rsqrtf(t / (float)L + 1e-6f);
    }
    __syncthreads();
    float inv = s_inv;
    for (int c = threadIdx.x; c < L; c += blockDim.x) {
        float val = w[c] * (x[c] * inv);
        bf16 hi = __float2bfloat16(val);
        bf16 lo = __float2bfloat16(val - __bfloat162float(hi));
        Yh[(size_t)row * L + c] = hi;
        Yl[(size_t)row * L + c] = lo;
    }
}

// ---------------- HMMA flash attention (causal, split-bf16, double-buffered K/V) ----------------
// CTA: 128 q-rows x 1 head, 8 warps x m16. K/V streamed in 32-key blocks, 2 stages.
#define FQ 128
#define FK 32
#define QSTRB 400
#define VSTRB 272
#define SQH 0
#define SQL 51200
#define SK  102400           // 2 stages x (hi 12800 + lo 12800)
#define KSTAGE 25600
#define SV  153600           // 2 stages x (hi 8704 + lo 8704)
#define VSTAGE 17408
#define FLASH_SMEM 188416

__global__ void __launch_bounds__(256, 1) mla_flash_mma(
    const bf16* __restrict__ Qh, const bf16* __restrict__ Ql,
    const bf16* __restrict__ Kh, const bf16* __restrict__ Kl,
    const bf16* __restrict__ Vh, const bf16* __restrict__ Vl,
    bf16* __restrict__ Oh, bf16* __restrict__ Ol)
{
    extern __shared__ __align__(1024) char fs[];
    const uint32_t smb = smem_u32(fs);

    const int h = blockIdx.y;
    const int qb = blockIdx.x;
    const int qbase = qb * FQ;
    const int tid = threadIdx.x;
    const int lane = tid & 31;
    const int wid = tid >> 5;
    const int row_min = qbase + wid * 16;

    // ---- load Q tile (hi+lo) ----
    for (int i = tid; i < FQ * 24; i += 256) {
        int r = i / 24, c = i % 24;
        size_t go = ((size_t)(qbase + r) * H_N + h) * QK_D + c * 8;
        uint32_t so = (uint32_t)(r * QSTRB + c * 16);
        CP_ASYNC16(smb + SQH + so, Qh + go, 16);
        CP_ASYNC16(smb + SQL + so, Ql + go, 16);
    }
    CP_COMMIT();

    auto load_kv = [&](int s, int kbase) {
        uint32_t kbp = smb + SK + s * KSTAGE;
        uint32_t vbp = smb + SV + s * VSTAGE;
#pragma unroll
        for (int it = 0; it < 3; it++) {
            int i = tid + it * 256;          // 0..767
            int r = i / 24, c = i % 24;
            size_t go = ((size_t)(kbase + r) * H_N + h) * QK_D + c * 8;
            uint32_t so = (uint32_t)(r * QSTRB + c * 16);
            CP_ASYNC16(kbp + so, Kh + go, 16);
            CP_ASYNC16(kbp + 12800 + so, Kl + go, 16);
        }
#pragma unroll
        for (int it = 0; it < 2; it++) {
            int i = tid + it * 256;          // 0..511
            int r = i >> 4, c = i & 15;
            size_t go = ((size_t)(kbase + r) * H_N + h) * VH_D + c * 8;
            uint32_t so = (uint32_t)(r * VSTRB + c * 16);
            CP_ASYNC16(vbp + so, Vh + go, 16);
            CP_ASYNC16(vbp + 8704 + so, Vl + go, 16);
        }
        CP_COMMIT();
    };

    // per-thread fragment base offsets (relative to stage hi base)
    const uint32_t qfb = smb + SQH + (uint32_t)((wid * 16 + (lane & 15)) * QSTRB + (lane >> 4) * 16);
    const uint32_t kfrel = (uint32_t)((lane & 15) * QSTRB + (lane >> 4) * 16);
    const uint32_t vfrel = (uint32_t)((lane & 15) * VSTRB + (lane >> 4) * 16);

    float o[16][4];
#pragma unroll
    for (int g = 0; g < 16; g++)
#pragma unroll
        for (int j = 0; j < 4; j++) o[g][j] = 0.f;
    float m0 = -1e30f, m1 = -1e30f, l0 = 0.f, l1 = 0.f;
    const float scale = 0.07216878364870322f;

    const int nkb = 4 * (qb + 1);
    load_kv(0, 0);

    int buf = 0;
    for (int kb = 0; kb < nkb; kb++) {
        const int kbase = kb * FK;
        if (kb + 1 < nkb) {
            load_kv(buf ^ 1, (kb + 1) * FK);
            CP_WAIT(1);
        } else {
            CP_WAIT(0);
        }
        __syncthreads();

        if (kbase <= row_min) {   // active: every covered row has >=1 visible key
            uint32_t kst = smb + SK + buf * KSTAGE;
            uint32_t vst = smb + SV + buf * VSTAGE;

            // ---- S = Q K^T (3 split passes fused per ks) ----
            float c[4][4];
#pragma unroll
            for (int g = 0; g < 4; g++)
#pragma unroll
                for (int j = 0; j < 4; j++) c[g][j] = 0.f;

#pragma unroll
            for (int ks = 0; ks < 12; ks++) {
                uint32_t ah[4], al[4];
                ldsm4(qfb + ks * 32, ah);
                ldsm4(qfb + (SQL - SQH) + ks * 32, al);
#pragma unroll
                for (int gg = 0; gg < 2; gg++) {
                    uint32_t bh[4], bl[4];
                    ldsm4(kst + kfrel + gg * (16 * QSTRB) + ks * 32, bh);
                    ldsm4(kst + 12800 + kfrel + gg * (16 * QSTRB) + ks * 32, bl);
                    MMA16816(c[2 * gg],     ah, bh[0], bh[2]);
                    MMA16816(c[2 * gg + 1], ah, bh[1], bh[3]);
                    MMA16816(c[2 * gg],     ah, bl[0], bl[2]);
                    MMA16816(c[2 * gg + 1], ah, bl[1], bl[3]);
                    MMA16816(c[2 * gg],     al, bh[0], bh[2]);
                    MMA16816(c[2 * gg + 1], al, bh[1], bh[3]);
                }
            }

            // ---- scale + causal mask ----
            const int row0 = row_min + (lane >> 2);
            const bool needmask = (kbase + FK - 1 > row_min);
#pragma unroll
            for (int g = 0; g < 4; g++) {
                int col = kbase + g * 8 + (lane & 3) * 2;
#pragma unroll
                for (int j = 0; j < 4; j++) {
                    float v = c[g][j] * scale;
                    if (needmask) {
                        int cc = col + (j & 1);
                        int rr = row0 + ((j >> 1) << 3);
                        if (cc > rr) v = -1e30f;
                    }
                    c[g][j] = v;
                }
            }

            // ---- online softmax ----
            float mx0 = -1e30f, mx1 = -1e30f;
#pragma unroll
            for (int g = 0; g < 4; g++) {
                mx0 = fmaxf(mx0, fmaxf(c[g][0], c[g][1]));
                mx1 = fmaxf(mx1, fmaxf(c[g][2], c[g][3]));
            }
#pragma unroll
            for (int off = 1; off < 4; off <<= 1) {
                mx0 = fmaxf(mx0, __shfl_xor_sync(0xffffffffu, mx0, off));
                mx1 = fmaxf(mx1, __shfl_xor_sync(0xffffffffu, mx1, off));
            }
            float mn0 = fmaxf(m0, mx0), mn1 = fmaxf(m1, mx1);
            float al0 = __expf(m0 - mn0), al1 = __expf(m1 - mn1);
            float rs0 = 0.f, rs1 = 0.f;
#pragma unroll
            for (int g = 0; g < 4; g++) {
                c[g][0] = __expf(c[g][0] - mn0); rs0 += c[g][0];
                c[g][1] = __expf(c[g][1] - mn0); rs0 += c[g][1];
                c[g][2] = __expf(c[g][2] - mn1); rs1 += c[g][2];
                c[g][3] = __expf(c[g][3] - mn1); rs1 += c[g][3];
            }
#pragma unroll
            for (int off = 1; off < 4; off <<= 1) {
                rs0 += __shfl_xor_sync(0xffffffffu, rs0, off);
                rs1 += __shfl_xor_sync(0xffffffffu, rs1, off);
            }
            l0 = l0 * al0 + rs0; l1 = l1 * al1 + rs1;
            m0 = mn0; m1 = mn1;
#pragma unroll
            for (int g = 0; g < 16; g++) {
                o[g][0] *= al0; o[g][1] *= al0;
                o[g][2] *= al1; o[g][3] *= al1;
            }

            // ---- O += P V (P register-resident, split hi/lo) ----
#pragma unroll
            for (int kc = 0; kc < 2; kc++) {
                uint32_t aph[4], apl[4];
                split2(c[2 * kc][0],     c[2 * kc][1],     aph[0], apl[0]);
                split2(c[2 * kc][2],     c[2 * kc][3],     aph[1], apl[1]);
                split2(c[2 * kc + 1][0], c[2 * kc + 1][1], aph[2], apl[2]);
                split2(c[2 * kc + 1][2], c[2 * kc + 1][3], aph[3], apl[3]);
#pragma unroll
                for (int ng = 0; ng < 8; ng++) {
                    uint32_t vh4[4], vl4[4];
                    ldsm4t(vst + vfrel + kc * (16 * VSTRB) + ng * 32, vh4);
                    ldsm4t(vst + 8704 + vfrel + kc * (16 * VSTRB) + ng * 32, vl4);
                    MMA16816(o[2 * ng],     aph, vh4[0], vh4[1]);
                    MMA16816(o[2 * ng + 1], aph, vh4[2], vh4[3]);
                    MMA16816(o[2 * ng],     aph, vl4[0], vl4[1]);
                    MMA16816(o[2 * ng + 1], aph, vl4[2], vl4[3]);
                    MMA16816(o[2 * ng],     apl, vh4[0], vh4[1]);
                    MMA16816(o[2 * ng + 1], apl, vh4[2], vh4[3]);
                }
            }
        }
        __syncthreads();
        buf ^= 1;
    }

    // ---- write O (split bf16 for wo GEMM) ----
    float inv0 = 1.0f / l0, inv1 = 1.0f / l1;
    int row0 = row_min + (lane >> 2);
#pragma unroll
    for (int g = 0; g < 16; g++) {
        int col = h * VH_D + g * 8 + (lane & 3) * 2;
        uint32_t hh, ll;
        split2(o[g][0] * inv0, o[g][1] * inv0, hh, ll);
        *(uint32_t*)(Oh + (size_t)row0 * ATTN_N + col) = hh;
        *(uint32_t*)(Ol + (size_t)row0 * ATTN_N + col) = ll;
        split2(o[g][2] * inv1, o[g][3] * inv1, hh, ll);
        *(uint32_t*)(Oh + (size_t)(row0 + 8) * ATTN_N + col) = hh;
        *(uint32_t*)(Ol + (size_t)(row0 + 8) * ATTN_N + col) = ll;
    }
}

// ---------------- launch ----------------
static inline void split_launch(const float* src, bf16* h, bf16* l, int n) {
    int n4 = n / 4;
    split_f32<<<(n4 + 255) / 256, 256>>>(src, h, l, n4);
}

extern "C" void kernel_launch(void* const* d_in, const int* in_sizes, int n_in,
                              void* d_out, int out_size)
{
    const float* x          = (const float*)d_in[0];
    const float* fcos       = (const float*)d_in[2];
    const float* fsin       = (const float*)d_in[3];
    const float* wq_down_w  = (const float*)d_in[5];
    const float* wq_down_b  = (const float*)d_in[6];
    const float* q_norm_w   = (const float*)d_in[7];
    const float* wq_up_w    = (const float*)d_in[8];
    const float* wq_up_b    = (const float*)d_in[9];
    const float* wkv_down_w = (const float*)d_in[10];
    const float* wkv_down_b = (const float*)d_in[11];
    const float* kv_norm_w  = (const float*)d_in[12];
    const float* wkv_up_w   = (const float*)d_in[13];
    const float* wkv_up_b   = (const float*)d_in[14];
    const float* wo_w       = (const float*)d_in[15];
    const float* wo_b       = (const float*)d_in[16];
    float* out = (float*)d_out;

    float *qdown, *q, *kv, *kvup;
    bf16 *xh, *xl, *qdnh, *qdnl, *kvnh, *kvnl, *attnh, *attnl;
    bf16 *qfh, *qfl, *kfh, *kfl, *vfh, *vfl;
    bf16 *wqdh, *wqdl, *wkvdh, *wkvdl, *wquh, *wqul, *wkvuh, *wkvul, *woh, *wol;
    cudaGetSymbolAddress((void**)&qdown, g_qdown);
    cudaGetSymbolAddress((void**)&q,     g_q);
    cudaGetSymbolAddress((void**)&kv,    g_kv);
    cudaGetSymbolAddress((void**)&kvup,  g_kvup);
    cudaGetSymbolAddress((void**)&xh, g_xh);       cudaGetSymbolAddress((void**)&xl, g_xl);
    cudaGetSymbolAddress((void**)&qdnh, g_qdnh);   cudaGetSymbolAddress((void**)&qdnl, g_qdnl);
    cudaGetSymbolAddress((void**)&kvnh, g_kvnh);   cudaGetSymbolAddress((void**)&kvnl, g_kvnl);
    cudaGetSymbolAddress((void**)&attnh, g_attnh); cudaGetSymbolAddress((void**)&attnl, g_attnl);
    cudaGetSymbolAddress((void**)&qfh, g_qfh);     cudaGetSymbolAddress((void**)&qfl, g_qfl);
    cudaGetSymbolAddress((void**)&kfh, g_kfh);     cudaGetSymbolAddress((void**)&kfl, g_kfl);
    cudaGetSymbolAddress((void**)&vfh, g_vfh);     cudaGetSymbolAddress((void**)&vfl, g_vfl);
    cudaGetSymbolAddress((void**)&wqdh, g_wqdh);   cudaGetSymbolAddress((void**)&wqdl, g_wqdl);
    cudaGetSymbolAddress((void**)&wkvdh, g_wkvdh); cudaGetSymbolAddress((void**)&wkvdl, g_wkvdl);
    cudaGetSymbolAddress((void**)&wquh, g_wquh);   cudaGetSymbolAddress((void**)&wqul, g_wqul);
    cudaGetSymbolAddress((void**)&wkvuh, g_wkvuh); cudaGetSymbolAddress((void**)&wkvul, g_wkvul);
    cudaGetSymbolAddress((void**)&woh, g_woh);     cudaGetSymbolAddress((void**)&wol, g_wol);

    cudaFuncSetAttribute(gemm_mma, cudaFuncAttributeMaxDynamicSharedMemorySize, GM_SMEM);
    cudaFuncSetAttribute(mla_flash_mma, cudaFuncAttributeMaxDynamicSharedMemorySize, FLASH_SMEM);

    // splits (inputs + weights)
    split_launch(x,          xh,    xl,    S_LEN * D_DIM);
    split_launch(wq_down_w,  wqdh,  wqdl,  QLORA * D_DIM);
    split_launch(wkv_down_w, wkvdh, wkvdl, KVD * D_DIM);
    split_launch(wq_up_w,    wquh,  wqul,  QUP_N * QLORA);
    split_launch(wkv_up_w,   wkvuh, wkvul, KVUP_N * KVLORA);
    split_launch(wo_w,       woh,   wol,   D_DIM * ATTN_N);

    // projections
    gemm_mma<<<dim3(QLORA / 128, S_LEN / 128), 256, GM_SMEM>>>(
        xh, xl, wqdh, wqdl, wq_down_b, qdown, QLORA, D_DIM);
    gemm_mma<<<dim3((KVD + 127) / 128, S_LEN / 128), 256, GM_SMEM>>>(
        xh, xl, wkvdh, wkvdl, wkv_down_b, kv, KVD, D_DIM);
    mla_rmsnorm_split<<<S_LEN, 256>>>(qdown, QLORA, q_norm_w, qdnh, qdnl, QLORA);
    mla_rmsnorm_split<<<S_LEN, 256>>>(kv, KVD, kv_norm_w, kvnh, kvnl, KVLORA);
    gemm_mma<<<dim3(QUP_N / 128, S_LEN / 128), 256, GM_SMEM>>>(
        qdnh, qdnl, wquh, wqul, wq_up_b, q, QUP_N, QLORA);
    gemm_mma<<<dim3(KVUP_N / 128, S_LEN / 128), 256, GM_SMEM>>>(
        kvnh, kvnl, wkvuh, wkvul, wkv_up_b, kvup, KVUP_N, KVLORA);

    // fused rope + split/pack to bf16 hi/lo
    rope_split_q<<<(S_LEN * H_N * 24) / 256, 256>>>(q, fcos, fsin, qfh, qfl);
    pack_k<<<(S_LEN * H_N * 24) / 256, 256>>>(kvup, kv, fcos, fsin, kfh, kfl);
    pack_v<<<(S_LEN * H_N * 16) / 256, 256>>>(kvup, vfh, vfl);

    // HMMA flash attention (double-buffered K/V)
    mla_flash_mma<<<dim3(S_LEN / FQ, H_N), 256, FLASH_SMEM>>>(
        qfh, qfl, kfh, kfl, vfh, vfl, attnh, attnl);

    // output projection
    gemm_mma<<<dim3(D_DIM / 128, S_LEN / 128), 256, GM_SMEM>>>(
        attnh, attnl, woh, wol, wo_b, out, D_DIM, ATTN_N);
}